// round 14
// baseline (speedup 1.0000x reference)
#include <cuda_runtime.h>
#include <cuda_fp16.h>
#include <math.h>
#include <stdint.h>

#define BSZ   2
#define SEQ   2048
#define DM    2048
#define NH    16
#define HDIM  128
#define HID   5632
#define NTOK  (BSZ*SEQ)     // 4096
#define HTOK  (NTOK/2)      // 2048 rows per batch half
#define QKVN  (3*DM)        // 6144
#define FFN2  (2*HID)       // 11264

// ---------------- scratch (no allocation allowed -> __device__ globals) ----
__device__ __half g_xn  [NTOK*(size_t)DM];
__device__ __half g_qkv [NTOK*(size_t)QKVN];
__device__ __half g_attn[NTOK*(size_t)DM];
__device__ float  g_h   [NTOK*(size_t)DM];
__device__ __half g_hn  [NTOK*(size_t)DM];
__device__ __half g_ffa [NTOK*(size_t)HID];
// fp16 weights, [K,N] layout (wq|wk|wv fused; w1/w3 interleaved by 8 cols)
__device__ __half g_wqkv[DM*(size_t)QKVN];
__device__ __half g_wo  [DM*(size_t)DM];
__device__ __half g_w13 [DM*(size_t)FFN2];
__device__ __half g_w2  [HID*(size_t)DM];

// ---------------- streams/events created at static init (pre-checkpoint) ---
static cudaStream_t g_s1, g_s2, g_s3;
static cudaEvent_t  g_e0, g_eQ, g_eW, g_eF, g_e1, g_e2;
static struct StreamInit {
    StreamInit(){
        cudaStreamCreateWithFlags(&g_s1, cudaStreamNonBlocking);
        cudaStreamCreateWithFlags(&g_s2, cudaStreamNonBlocking);
        cudaStreamCreateWithFlags(&g_s3, cudaStreamNonBlocking);
        cudaEventCreateWithFlags(&g_e0, cudaEventDisableTiming);
        cudaEventCreateWithFlags(&g_eQ, cudaEventDisableTiming);
        cudaEventCreateWithFlags(&g_eW, cudaEventDisableTiming);
        cudaEventCreateWithFlags(&g_eF, cudaEventDisableTiming);
        cudaEventCreateWithFlags(&g_e1, cudaEventDisableTiming);
        cudaEventCreateWithFlags(&g_e2, cudaEventDisableTiming);
    }
} g_stream_init;

// ---------------- helpers --------------------------------------------------
__device__ __forceinline__ uint32_t smem_u32(const void* p){
    uint32_t a;
    asm("{ .reg .u64 t; cvta.to.shared.u64 t, %1; cvt.u32.u64 %0, t; }" : "=r"(a) : "l"(p));
    return a;
}
__device__ __forceinline__ void cp16(void* dst, const void* src){
    unsigned d = (unsigned)__cvta_generic_to_shared(dst);
    asm volatile("cp.async.cg.shared.global [%0], [%1], 16;" :: "r"(d), "l"(src));
}
__device__ __forceinline__ void cp_commit(){ asm volatile("cp.async.commit_group;"); }
__device__ __forceinline__ void cp_wait0(){ asm volatile("cp.async.wait_group 0;"); }
__device__ __forceinline__ void cp_wait1(){ asm volatile("cp.async.wait_group 1;"); }
__device__ __forceinline__ void cp_wait2(){ asm volatile("cp.async.wait_group 2;"); }

__device__ __forceinline__ void ldm4(uint32_t r[4], uint32_t addr){
    asm volatile("ldmatrix.sync.aligned.m8n8.x4.shared.b16 {%0,%1,%2,%3}, [%4];"
        : "=r"(r[0]), "=r"(r[1]), "=r"(r[2]), "=r"(r[3]) : "r"(addr));
}
__device__ __forceinline__ void ldm4t(uint32_t r[4], uint32_t addr){
    asm volatile("ldmatrix.sync.aligned.m8n8.x4.trans.shared.b16 {%0,%1,%2,%3}, [%4];"
        : "=r"(r[0]), "=r"(r[1]), "=r"(r[2]), "=r"(r[3]) : "r"(addr));
}
__device__ __forceinline__ void mma_f16(float c[4], const uint32_t a[4], uint32_t b0, uint32_t b1){
    asm volatile("mma.sync.aligned.m16n8k16.row.col.f32.f16.f16.f32 "
        "{%0,%1,%2,%3},{%4,%5,%6,%7},{%8,%9},{%0,%1,%2,%3};"
        : "+f"(c[0]), "+f"(c[1]), "+f"(c[2]), "+f"(c[3])
        : "r"(a[0]), "r"(a[1]), "r"(a[2]), "r"(a[3]), "r"(b0), "r"(b1));
}
__device__ __forceinline__ uint32_t pkh2(float a, float b){
    __half2 h = __floats2half2_rn(a, b);
    return reinterpret_cast<uint32_t&>(h);
}
__device__ __forceinline__ float siluf(float x){ return x / (1.f + __expf(-x)); }
// swizzles (relative byte offsets; conflict-free ldmatrix phases)
__device__ __forceinline__ uint32_t swA(uint32_t o){ return o ^ (((o >> 7) & 7) << 4); }   // 128B rows
__device__ __forceinline__ uint32_t sw256(uint32_t o){ return o ^ (((o >> 8) & 7) << 4); } // 256B rows

// ------- weight convert prepass: fp32[K,Ns] -> fp16 ------------------------
__device__ __forceinline__ void cvt8_body(const float* __restrict__ src, __half* __restrict__ dst,
                                          int Ns, int Nd, int col0, int total8){
    int idx = blockIdx.x*blockDim.x + threadIdx.x;
    if (idx >= total8) return;
    int ns8 = Ns >> 3;
    int k = idx / ns8, j = (idx - k*ns8) << 3;
    const float4* s = (const float4*)(src + (size_t)k*Ns + j);
    float4 v0 = s[0], v1 = s[1];
    uint4 o;
    o.x = pkh2(v0.x, v0.y); o.y = pkh2(v0.z, v0.w);
    o.z = pkh2(v1.x, v1.y); o.w = pkh2(v1.z, v1.w);
    *(uint4*)(dst + (size_t)k*Nd + j + col0) = o;
}

// qkv convert: 16 elems/thread, 2x uint4 stores (high MLP, critical path head)
__global__ void cvt_qkv(const float* wq, const float* wk, const float* wv, __half* dst){
    const float* srcs[3] = {wq, wk, wv};
    const float* src = srcs[blockIdx.y];
    int idx = blockIdx.x*blockDim.x + threadIdx.x;
    if (idx >= DM*DM/16) return;
    int ns16 = DM >> 4;
    int k = idx / ns16, j = (idx - k*ns16) << 4;
    const float4* s = (const float4*)(src + (size_t)k*DM + j);
    float4 v0 = s[0], v1 = s[1], v2 = s[2], v3 = s[3];
    uint4 o0, o1;
    o0.x = pkh2(v0.x,v0.y); o0.y = pkh2(v0.z,v0.w);
    o0.z = pkh2(v1.x,v1.y); o0.w = pkh2(v1.z,v1.w);
    o1.x = pkh2(v2.x,v2.y); o1.y = pkh2(v2.z,v2.w);
    o1.z = pkh2(v3.x,v3.y); o1.w = pkh2(v3.z,v3.w);
    __half* d = dst + (size_t)k*QKVN + blockIdx.y*DM + j;
    *(uint4*)(d)     = o0;
    *(uint4*)(d + 8) = o1;
}
// w1/w3 interleaved by 8 cols; contiguous 32B stores
__global__ void cvt_w13(const float* __restrict__ w1, const float* __restrict__ w3,
                        __half* __restrict__ dst){
    int idx = blockIdx.x*blockDim.x + threadIdx.x;
    const int total8 = DM*HID/8;
    if (idx >= total8) return;
    int ns8 = HID >> 3;
    int k = idx / ns8, j8 = idx - k*ns8;
    const float4* a = (const float4*)(w1 + (size_t)k*HID + j8*8);
    const float4* b = (const float4*)(w3 + (size_t)k*HID + j8*8);
    float4 a0 = a[0], a1 = a[1];
    float4 b0 = b[0], b1 = b[1];
    uint4 o1 = make_uint4(pkh2(a0.x,a0.y), pkh2(a0.z,a0.w), pkh2(a1.x,a1.y), pkh2(a1.z,a1.w));
    uint4 o3 = make_uint4(pkh2(b0.x,b0.y), pkh2(b0.z,b0.w), pkh2(b1.x,b1.y), pkh2(b1.z,b1.w));
    __half* d = dst + (size_t)k*FFN2 + j8*16;
    *(uint4*)(d)     = o1;
    *(uint4*)(d + 8) = o3;
}
__global__ void cvt_ow2(const float* wo, const float* w2, __half* dwo, __half* dw2){
    if (blockIdx.y == 0) cvt8_body(wo, dwo, DM, DM, 0, DM*DM/8);
    else                 cvt8_body(w2, dw2, DM, DM, 0, HID*DM/8);
}

// ---------------- rmsnorm (fp32 in -> fp16 out, vectorized) ----------------
__global__ void rmsnorm_kernel(const float* __restrict__ x, const float* __restrict__ w,
                               __half* __restrict__ out){
    int row = blockIdx.x;
    const float4* xr = (const float4*)(x + (size_t)row*DM);
    float4 v0 = xr[threadIdx.x], v1 = xr[threadIdx.x + 256];
    float ss = v0.x*v0.x + v0.y*v0.y + v0.z*v0.z + v0.w*v0.w
             + v1.x*v1.x + v1.y*v1.y + v1.z*v1.z + v1.w*v1.w;
    __shared__ float red[8];
    #pragma unroll
    for (int o = 16; o; o >>= 1) ss += __shfl_xor_sync(~0u, ss, o);
    if ((threadIdx.x & 31) == 0) red[threadIdx.x >> 5] = ss;
    __syncthreads();
    if (threadIdx.x == 0){
        float t = 0.f;
        #pragma unroll
        for (int i = 0; i < 8; i++) t += red[i];
        red[0] = t;
    }
    __syncthreads();
    float inv = rsqrtf(red[0] / (float)DM + 1e-5f);
    const float4* w4 = (const float4*)w;
    uint2* o2 = (uint2*)(out + (size_t)row*DM);
    float4 a = w4[threadIdx.x], b = w4[threadIdx.x + 256];
    o2[threadIdx.x]       = make_uint2(pkh2(v0.x*inv*a.x, v0.y*inv*a.y), pkh2(v0.z*inv*a.z, v0.w*inv*a.w));
    o2[threadIdx.x + 256] = make_uint2(pkh2(v1.x*inv*b.x, v1.y*inv*b.y), pkh2(v1.z*inv*b.z, v1.w*inv*b.w));
}

// ================= fp16 GEMM: C[M,N] = A[M,K] @ B[K,N] =====================
// 128x128 block, 4 warps of 64x64, BK=64, 3-stage cp.async, 2 CTAs/SM.
#define GSTG_BYTES (32*1024)
#define GEMM_SMEM  (3*GSTG_BYTES)     // 98304 -> 2 CTAs/SM
#define QSCALE 0.08838834764831845f   // 1/sqrt(128), folded into Q

template<bool ADD, bool HOUT, bool ROPE, bool SILU>
__global__ void __launch_bounds__(128, 2)
gemm_kernel(const __half* __restrict__ A, const __half* __restrict__ B,
            const float* __restrict__ Add, void* __restrict__ Cv,
            int M, int N, int K,
            const float* __restrict__ fc, const float* __restrict__ fs)
{
    extern __shared__ char smem[];
    const uint32_t sb = smem_u32(smem);
    const int tid = threadIdx.x, lane = tid & 31, wid = tid >> 5;   // 4 warps
    const int wm = (wid >> 1) * 64;
    const int wn = (wid & 1) * 64;
    const int bm = blockIdx.y * 128, bn = blockIdx.x * 128;

    float acc[4][8][4];
    #pragma unroll
    for (int i=0;i<4;i++)
        #pragma unroll
        for (int j=0;j<8;j++)
            #pragma unroll
            for (int r=0;r<4;r++) acc[i][j][r] = 0.f;

    const int nk = K / 64;

    auto issue = [&](int kt, int st){
        char* Ad = smem + st*GSTG_BYTES;
        const __half* Ag = A + (size_t)bm*K + kt*64;
        #pragma unroll
        for (int i = 0; i < 8; i++){
            int idx = tid + i*128;            // 0..1023
            int m = idx >> 3, c = idx & 7;
            cp16(Ad + swA(m*128 + c*16), Ag + (size_t)m*K + c*8);
        }
        char* Bd = Ad + 16*1024;
        const __half* Bg = B + (size_t)(kt*64)*N + bn;
        #pragma unroll
        for (int i = 0; i < 8; i++){
            int idx = tid + i*128;            // 0..1023
            int k = idx >> 4, c = idx & 15;
            cp16(Bd + sw256(k*256 + c*16), Bg + (size_t)k*N + c*8);
        }
        cp_commit();
    };

    issue(0, 0); issue(1, 1);
    int cur = 0, nxt = 2;
    for (int kt = 0; kt < nk; kt++){
        cp_wait1();
        __syncthreads();
        if (kt+2 < nk) issue(kt+2, nxt);
        const uint32_t sA = sb + cur*GSTG_BYTES;
        const uint32_t sB = sA + 16*1024;
        if (++cur == 3) cur = 0;
        if (++nxt == 3) nxt = 0;
        #pragma unroll
        for (int ks = 0; ks < 4; ks++){
            uint32_t af[4][4];
            #pragma unroll
            for (int mt = 0; mt < 4; mt++){
                int row = wm + mt*16 + (lane&7) + ((lane>>3)&1)*8;
                int ch  = 2*ks + (lane>>4);
                ldm4(af[mt], sA + swA(row*128 + ch*16));
            }
            uint32_t bf[4][4];
            #pragma unroll
            for (int ntp = 0; ntp < 4; ntp++){
                int krow = ks*16 + (lane&7) + ((lane>>3)&1)*8;
                int ch   = ((wn + ntp*16) >> 3) + (lane>>4);
                ldm4t(bf[ntp], sB + sw256(krow*256 + ch*16));
            }
            #pragma unroll
            for (int mt = 0; mt < 4; mt++)
                #pragma unroll
                for (int ntp = 0; ntp < 4; ntp++){
                    mma_f16(acc[mt][2*ntp],   af[mt], bf[ntp][0], bf[ntp][1]);
                    mma_f16(acc[mt][2*ntp+1], af[mt], bf[ntp][2], bf[ntp][3]);
                }
        }
    }

    // ---------------- epilogue ----------------
    if (SILU){
        __half* C = (__half*)Cv;
        const int NO = N >> 1;    // HID
        #pragma unroll
        for (int mt = 0; mt < 4; mt++){
            int r0 = bm + wm + mt*16 + (lane>>2);
            #pragma unroll
            for (int ntp = 0; ntp < 4; ntp++){
                int j = ((bn + wn) >> 1) + ntp*8 + (lane&3)*2;
                const float* a1 = acc[mt][2*ntp];
                const float* a3 = acc[mt][2*ntp+1];
                *(uint32_t*)(C + (size_t)r0*NO + j) =
                    pkh2(siluf(a1[0])*a3[0], siluf(a1[1])*a3[1]);
                *(uint32_t*)(C + (size_t)(r0+8)*NO + j) =
                    pkh2(siluf(a1[2])*a3[2], siluf(a1[3])*a3[3]);
            }
        }
        return;
    }
    #pragma unroll
    for (int mt = 0; mt < 4; mt++){
        #pragma unroll
        for (int nt = 0; nt < 8; nt++){
            int r = bm + wm + mt*16 + (lane>>2);
            int c = bn + wn + nt*8 + (lane&3)*2;
            float2 v0 = make_float2(acc[mt][nt][0], acc[mt][nt][1]);
            float2 v1 = make_float2(acc[mt][nt][2], acc[mt][nt][3]);
            if (ADD){
                const float* A0 = Add + (size_t)r*N + c;
                const float* A1 = Add + (size_t)(r+8)*N + c;
                v0.x += A0[0]; v0.y += A0[1];
                v1.x += A1[0]; v1.y += A1[1];
            }
            if (ROPE && c < 2*DM){
                int i = (c & (HDIM-1)) >> 1;
                int s0 = r & (SEQ-1), s1 = (r+8) & (SEQ-1);
                float c0 = fc[s0*64 + i], sn0 = fs[s0*64 + i];
                float c1 = fc[s1*64 + i], sn1 = fs[s1*64 + i];
                float a = v0.x, b = v0.y;
                v0.x = a*c0 - b*sn0; v0.y = a*sn0 + b*c0;
                a = v1.x; b = v1.y;
                v1.x = a*c1 - b*sn1; v1.y = a*sn1 + b*c1;
                if (c < DM){   // q slice: fold softmax scale
                    v0.x *= QSCALE; v0.y *= QSCALE;
                    v1.x *= QSCALE; v1.y *= QSCALE;
                }
            }
            if (HOUT){
                __half* C = (__half*)Cv;
                *(uint32_t*)(C + (size_t)r*N + c)     = pkh2(v0.x, v0.y);
                *(uint32_t*)(C + (size_t)(r+8)*N + c) = pkh2(v1.x, v1.y);
            } else {
                float* C = (float*)Cv;
                *(float2*)(C + (size_t)r*N + c)     = v0;
                *(float2*)(C + (size_t)(r+8)*N + c) = v1;
            }
        }
    }
}

// ---------------- flash attention, BQ=128, 256 threads ---------------------
// 3-stage KV ring: stage bases {32K, 64K, 0K} (stage 2 recycles the Q buffer
// after Q is consumed into registers). K at base, V at base+16K.
// Online softmax with rescale-skip when the running max is unchanged.
#define FLASH_SMEM (96*1024)

__global__ void __launch_bounds__(256)
flash_kernel(const __half* __restrict__ QKV, __half* __restrict__ O)
{
    extern __shared__ char smem[];
    const uint32_t sb = smem_u32(smem);
    const int tid = threadIdx.x, lane = tid & 31, wid = tid >> 5;
    const int qt = blockIdx.x, h = blockIdx.y;
    const int q0 = qt*128;

    auto kbase = [&](int s) -> uint32_t { return (s == 2) ? 0u : (uint32_t)((s+1) << 15); };

    {   // Q: 128 rows x 256B into [0,32K) (pre-scaled by 1/sqrt(HD))
        const __half* Qg = QKV + (size_t)q0*QKVN + h*HDIM;
        #pragma unroll
        for (int i = 0; i < 8; i++){
            int idx = tid + i*256;
            int r = idx >> 4, c = idx & 15;
            cp16(smem + sw256(r*256 + c*16), Qg + (size_t)r*QKVN + c*8);
        }
    }
    auto issueKV = [&](int kt, int st){
        const __half* Kg = QKV + (size_t)(kt*64)*QKVN + DM   + h*HDIM;
        const __half* Vg = QKV + (size_t)(kt*64)*QKVN + 2*DM + h*HDIM;
        char* Kd = smem + kbase(st);
        char* Vd = Kd + 16*1024;
        #pragma unroll
        for (int i = 0; i < 4; i++){
            int idx = tid + i*256;
            int r = idx >> 4, c = idx & 15;
            uint32_t so = sw256(r*256 + c*16);
            cp16(Kd + so, Kg + (size_t)r*QKVN + c*8);
            cp16(Vd + so, Vg + (size_t)r*QKVN + c*8);
        }
        cp_commit();
    };
    issueKV(0, 0);   // group 0 (includes Q)
    issueKV(1, 1);   // group 1
    cp_wait1();      // group 0 (Q + KV0) complete
    __syncthreads();

    uint32_t qf[8][4];
    #pragma unroll
    for (int ks = 0; ks < 8; ks++){
        int row = wid*16 + (lane&7) + ((lane>>3)&1)*8;
        int ch  = 2*ks + (lane>>4);
        ldm4(qf[ks], sb + sw256(row*256 + ch*16));
    }
    __syncthreads();   // all warps consumed Q -> safe to recycle [0,32K)
    issueKV(2, 2);     // group 2 into the Q buffer

    float m0 = -1e30f, m1 = -1e30f, l0 = 0.f, l1 = 0.f;
    float oacc[16][4];
    #pragma unroll
    for (int i=0;i<16;i++)
        #pragma unroll
        for (int j=0;j<4;j++) oacc[i][j] = 0.f;

    const int nkt = SEQ / 64;     // 32
    for (int kt = 0; kt < nkt; kt++){
        if (kt > 0){ cp_wait2(); __syncthreads(); }   // stage kt ready
        const uint32_t sK = sb + kbase(kt % 3);
        const uint32_t sV = sK + 16*1024;

        float sacc[8][4];
        #pragma unroll
        for (int i=0;i<8;i++)
            #pragma unroll
            for (int j=0;j<4;j++) sacc[i][j] = 0.f;
        #pragma unroll
        for (int ks = 0; ks < 8; ks++){
            #pragma unroll
            for (int ntp = 0; ntp < 4; ntp++){
                uint32_t kf[4];
                int row = ntp*16 + ((lane>>4)&1)*8 + (lane&7);
                int ch  = 2*ks + ((lane>>3)&1);
                ldm4(kf, sK + sw256(row*256 + ch*16));
                mma_f16(sacc[2*ntp],   qf[ks], kf[0], kf[1]);
                mma_f16(sacc[2*ntp+1], qf[ks], kf[2], kf[3]);
            }
        }

        float mx0 = -1e30f, mx1 = -1e30f;
        #pragma unroll
        for (int nt=0; nt<8; nt++){
            mx0 = fmaxf(mx0, fmaxf(sacc[nt][0], sacc[nt][1]));
            mx1 = fmaxf(mx1, fmaxf(sacc[nt][2], sacc[nt][3]));
        }
        mx0 = fmaxf(mx0, __shfl_xor_sync(~0u, mx0, 1));
        mx0 = fmaxf(mx0, __shfl_xor_sync(~0u, mx0, 2));
        mx1 = fmaxf(mx1, __shfl_xor_sync(~0u, mx1, 1));
        mx1 = fmaxf(mx1, __shfl_xor_sync(~0u, mx1, 2));
        float mn0 = fmaxf(m0, mx0), mn1 = fmaxf(m1, mx1);
        bool chg = (mn0 > m0) || (mn1 > m1);
        float rs0 = 0.f, rs1 = 0.f;
        #pragma unroll
        for (int nt=0; nt<8; nt++){
            sacc[nt][0] = __expf(sacc[nt][0] - mn0);
            sacc[nt][1] = __expf(sacc[nt][1] - mn0);
            sacc[nt][2] = __expf(sacc[nt][2] - mn1);
            sacc[nt][3] = __expf(sacc[nt][3] - mn1);
            rs0 += sacc[nt][0] + sacc[nt][1];
            rs1 += sacc[nt][2] + sacc[nt][3];
        }
        rs0 += __shfl_xor_sync(~0u, rs0, 1); rs0 += __shfl_xor_sync(~0u, rs0, 2);
        rs1 += __shfl_xor_sync(~0u, rs1, 1); rs1 += __shfl_xor_sync(~0u, rs1, 2);
        if (chg){
            float cr0 = __expf(m0 - mn0), cr1 = __expf(m1 - mn1);
            l0 = l0*cr0 + rs0; l1 = l1*cr1 + rs1;
            #pragma unroll
            for (int i=0;i<16;i++){
                oacc[i][0] *= cr0; oacc[i][1] *= cr0;
                oacc[i][2] *= cr1; oacc[i][3] *= cr1;
            }
            m0 = mn0; m1 = mn1;
        } else {
            l0 += rs0; l1 += rs1;
        }

        #pragma unroll
        for (int kv = 0; kv < 4; kv++){
            uint32_t pf[4];
            pf[0] = pkh2(sacc[2*kv][0],   sacc[2*kv][1]);
            pf[1] = pkh2(sacc[2*kv][2],   sacc[2*kv][3]);
            pf[2] = pkh2(sacc[2*kv+1][0], sacc[2*kv+1][1]);
            pf[3] = pkh2(sacc[2*kv+1][2], sacc[2*kv+1][3]);
            #pragma unroll
            for (int ntp = 0; ntp < 8; ntp++){
                uint32_t vf[4];
                int row = kv*16 + (lane&7) + ((lane>>3)&1)*8;
                int ch  = 2*ntp + (lane>>4);
                ldm4t(vf, sV + sw256(row*256 + ch*16));
                mma_f16(oacc[2*ntp],   pf, vf[0], vf[1]);
                mma_f16(oacc[2*ntp+1], pf, vf[2], vf[3]);
            }
        }

        __syncthreads();                                   // done reading stage kt
        if (kt+3 < nkt) issueKV(kt+3, (kt+3) % 3);         // safe overwrite
    }

    float inv0 = 1.f/l0, inv1 = 1.f/l1;
    int r = wid*16 + (lane>>2);
    __half* Og0 = O + ((size_t)(q0 + r))*DM + h*HDIM;
    __half* Og1 = O + ((size_t)(q0 + r + 8))*DM + h*HDIM;
    #pragma unroll
    for (int nt=0; nt<16; nt++){
        int c = nt*8 + (lane&3)*2;
        *(uint32_t*)(Og0 + c) = pkh2(oacc[nt][0]*inv0, oacc[nt][1]*inv0);
        *(uint32_t*)(Og1 + c) = pkh2(oacc[nt][2]*inv1, oacc[nt][3]*inv1);
    }
}

// ---------------- launch: 3-stream pipeline (split weight-ready events) -----
extern "C" void kernel_launch(void* const* d_in, const int* in_sizes, int n_in,
                              void* d_out, int out_size){
    const float* x   = (const float*)d_in[0];
    const float* fc  = (const float*)d_in[1];
    const float* fs  = (const float*)d_in[2];
    const float* wq  = (const float*)d_in[3];
    const float* wk  = (const float*)d_in[4];
    const float* wv  = (const float*)d_in[5];
    const float* wo  = (const float*)d_in[6];
    const float* w1  = (const float*)d_in[7];
    const float* w2  = (const float*)d_in[8];
    const float* w3  = (const float*)d_in[9];
    const float* anw = (const float*)d_in[10];
    const float* fnw = (const float*)d_in[11];
    float* out = (float*)d_out;

    __half *xn,*qkv,*attn,*hn,*ffa,*wqkvH,*woH,*w13H,*w2H;
    float  *h;
    cudaGetSymbolAddress((void**)&xn,    g_xn);
    cudaGetSymbolAddress((void**)&qkv,   g_qkv);
    cudaGetSymbolAddress((void**)&attn,  g_attn);
    cudaGetSymbolAddress((void**)&h,     g_h);
    cudaGetSymbolAddress((void**)&hn,    g_hn);
    cudaGetSymbolAddress((void**)&ffa,   g_ffa);
    cudaGetSymbolAddress((void**)&wqkvH, g_wqkv);
    cudaGetSymbolAddress((void**)&woH,   g_wo);
    cudaGetSymbolAddress((void**)&w13H,  g_w13);
    cudaGetSymbolAddress((void**)&w2H,   g_w2);

    cudaFuncSetAttribute((const void*)gemm_kernel<false,true,true,false>,  cudaFuncAttributeMaxDynamicSharedMemorySize, GEMM_SMEM);
    cudaFuncSetAttribute((const void*)gemm_kernel<true,false,false,false>, cudaFuncAttributeMaxDynamicSharedMemorySize, GEMM_SMEM);
    cudaFuncSetAttribute((const void*)gemm_kernel<false,true,false,true>,  cudaFuncAttributeMaxDynamicSharedMemorySize, GEMM_SMEM);
    cudaFuncSetAttribute((const void*)flash_kernel, cudaFuncAttributeMaxDynamicSharedMemorySize, FLASH_SMEM);

    const int thr = 256;
    const int t16 = DM*DM/16;     // 262144 (qkv 16-elem chunks)
    const int t8p = DM*HID/8;     // 1441792
    dim3 gq(QKVN/128, HTOK/128);  // (48,16)
    dim3 gd(DM/128,  HTOK/128);   // (16,16)
    dim3 gffh(FFN2/128, HTOK/128);// (88,16)
    dim3 gfl(SEQ/128, NH, 1);     // (16,16,1)

    // fork all three pipelines off the capture stream
    cudaEventRecord(g_e0, 0);
    cudaStreamWaitEvent(g_s1, g_e0, 0);
    cudaStreamWaitEvent(g_s2, g_e0, 0);
    cudaStreamWaitEvent(g_s3, g_e0, 0);

    // s3: weight converts in dependency order: qkv -> ow2 -> w13.
    cvt_qkv<<<dim3((t16+thr-1)/thr, 3), thr, 0, g_s3>>>(wq, wk, wv, wqkvH);
    cudaEventRecord(g_eQ, g_s3);
    cvt_ow2<<<dim3((t8p+thr-1)/thr, 2), thr, 0, g_s3>>>(wo, w2, woH, w2H);
    cudaEventRecord(g_eW, g_s3);
    cvt_w13<<<(t8p+thr-1)/thr, thr, 0, g_s3>>>(w1, w3, w13H);
    cudaEventRecord(g_eF, g_s3);

    // ---- stream 1: batch 0 (rows 0..2047) ----
    {
        const size_t r0 = 0;
        rmsnorm_kernel<<<HTOK, 256, 0, g_s1>>>(x + r0*DM, anw, xn + r0*DM);
        cudaStreamWaitEvent(g_s1, g_eQ, 0);
        gemm_kernel<false,true,true,false><<<gq, 128, GEMM_SMEM, g_s1>>>(
            xn + r0*DM, wqkvH, nullptr, qkv + r0*QKVN, HTOK, QKVN, DM, fc, fs);
        flash_kernel<<<gfl, 256, FLASH_SMEM, g_s1>>>(qkv + r0*QKVN, attn + r0*DM);
        cudaStreamWaitEvent(g_s1, g_eW, 0);
        gemm_kernel<true,false,false,false><<<gd, 128, GEMM_SMEM, g_s1>>>(
            attn + r0*DM, woH, x + r0*DM, h + r0*DM, HTOK, DM, DM, nullptr, nullptr);
        rmsnorm_kernel<<<HTOK, 256, 0, g_s1>>>(h + r0*DM, fnw, hn + r0*DM);
        cudaStreamWaitEvent(g_s1, g_eF, 0);
        gemm_kernel<false,true,false,true><<<gffh, 128, GEMM_SMEM, g_s1>>>(
            hn + r0*DM, w13H, nullptr, ffa + r0*HID, HTOK, FFN2, DM, nullptr, nullptr);
        gemm_kernel<true,false,false,false><<<gd, 128, GEMM_SMEM, g_s1>>>(
            ffa + r0*HID, w2H, h + r0*DM, out + r0*DM, HTOK, DM, HID, nullptr, nullptr);
        cudaEventRecord(g_e1, g_s1);
    }

    // ---- stream 2: batch 1 (rows 2048..4095) ----
    {
        const size_t r0 = HTOK;
        rmsnorm_kernel<<<HTOK, 256, 0, g_s2>>>(x + r0*DM, anw, xn + r0*DM);
        cudaStreamWaitEvent(g_s2, g_eQ, 0);
        gemm_kernel<false,true,true,false><<<gq, 128, GEMM_SMEM, g_s2>>>(
            xn + r0*DM, wqkvH, nullptr, qkv + r0*QKVN, HTOK, QKVN, DM, fc, fs);
        flash_kernel<<<gfl, 256, FLASH_SMEM, g_s2>>>(qkv + r0*QKVN, attn + r0*DM);
        cudaStreamWaitEvent(g_s2, g_eW, 0);
        gemm_kernel<true,false,false,false><<<gd, 128, GEMM_SMEM, g_s2>>>(
            attn + r0*DM, woH, x + r0*DM, h + r0*DM, HTOK, DM, DM, nullptr, nullptr);
        rmsnorm_kernel<<<HTOK, 256, 0, g_s2>>>(h + r0*DM, fnw, hn + r0*DM);
        cudaStreamWaitEvent(g_s2, g_eF, 0);
        gemm_kernel<false,true,false,true><<<gffh, 128, GEMM_SMEM, g_s2>>>(
            hn + r0*DM, w13H, nullptr, ffa + r0*HID, HTOK, FFN2, DM, nullptr, nullptr);
        gemm_kernel<true,false,false,false><<<gd, 128, GEMM_SMEM, g_s2>>>(
            ffa + r0*HID, w2H, h + r0*DM, out + r0*DM, HTOK, DM, HID, nullptr, nullptr);
        cudaEventRecord(g_e2, g_s2);
    }

    // join back to the capture stream
    cudaStreamWaitEvent(0, g_e1, 0);
    cudaStreamWaitEvent(0, g_e2, 0);
}

// round 15
// speedup vs baseline: 1.0006x; 1.0006x over previous
#include <cuda_runtime.h>
#include <cuda_fp16.h>
#include <math.h>
#include <stdint.h>

#define BSZ   2
#define SEQ   2048
#define DM    2048
#define NH    16
#define HDIM  128
#define HID   5632
#define NTOK  (BSZ*SEQ)     // 4096
#define HTOK  (NTOK/2)      // 2048 rows per batch half
#define QKVN  (3*DM)        // 6144
#define FFN2  (2*HID)       // 11264

// ---------------- scratch (no allocation allowed -> __device__ globals) ----
__device__ __half g_xn  [NTOK*(size_t)DM];
__device__ __half g_qkv [NTOK*(size_t)QKVN];
__device__ __half g_attn[NTOK*(size_t)DM];
__device__ float  g_h   [NTOK*(size_t)DM];
__device__ __half g_hn  [NTOK*(size_t)DM];
__device__ __half g_ffa [NTOK*(size_t)HID];
// fp16 weights, [K,N] layout (wq|wk|wv fused; w1/w3 interleaved by 8 cols)
__device__ __half g_wqkv[DM*(size_t)QKVN];
__device__ __half g_wo  [DM*(size_t)DM];
__device__ __half g_w13 [DM*(size_t)FFN2];
__device__ __half g_w2  [HID*(size_t)DM];

// ---------------- streams/events created at static init (pre-checkpoint) ---
static cudaStream_t g_s1, g_s2, g_s3;
static cudaEvent_t  g_e0, g_eQ, g_eW, g_eF, g_e1, g_e2;
static struct StreamInit {
    StreamInit(){
        cudaStreamCreateWithFlags(&g_s1, cudaStreamNonBlocking);
        cudaStreamCreateWithFlags(&g_s2, cudaStreamNonBlocking);
        cudaStreamCreateWithFlags(&g_s3, cudaStreamNonBlocking);
        cudaEventCreateWithFlags(&g_e0, cudaEventDisableTiming);
        cudaEventCreateWithFlags(&g_eQ, cudaEventDisableTiming);
        cudaEventCreateWithFlags(&g_eW, cudaEventDisableTiming);
        cudaEventCreateWithFlags(&g_eF, cudaEventDisableTiming);
        cudaEventCreateWithFlags(&g_e1, cudaEventDisableTiming);
        cudaEventCreateWithFlags(&g_e2, cudaEventDisableTiming);
    }
} g_stream_init;

// ---------------- helpers --------------------------------------------------
__device__ __forceinline__ uint32_t smem_u32(const void* p){
    uint32_t a;
    asm("{ .reg .u64 t; cvta.to.shared.u64 t, %1; cvt.u32.u64 %0, t; }" : "=r"(a) : "l"(p));
    return a;
}
__device__ __forceinline__ void cp16(void* dst, const void* src){
    unsigned d = (unsigned)__cvta_generic_to_shared(dst);
    asm volatile("cp.async.cg.shared.global [%0], [%1], 16;" :: "r"(d), "l"(src));
}
__device__ __forceinline__ void cp_commit(){ asm volatile("cp.async.commit_group;"); }
__device__ __forceinline__ void cp_wait0(){ asm volatile("cp.async.wait_group 0;"); }
__device__ __forceinline__ void cp_wait1(){ asm volatile("cp.async.wait_group 1;"); }

__device__ __forceinline__ void ldm4(uint32_t r[4], uint32_t addr){
    asm volatile("ldmatrix.sync.aligned.m8n8.x4.shared.b16 {%0,%1,%2,%3}, [%4];"
        : "=r"(r[0]), "=r"(r[1]), "=r"(r[2]), "=r"(r[3]) : "r"(addr));
}
__device__ __forceinline__ void ldm4t(uint32_t r[4], uint32_t addr){
    asm volatile("ldmatrix.sync.aligned.m8n8.x4.trans.shared.b16 {%0,%1,%2,%3}, [%4];"
        : "=r"(r[0]), "=r"(r[1]), "=r"(r[2]), "=r"(r[3]) : "r"(addr));
}
__device__ __forceinline__ void mma_f16(float c[4], const uint32_t a[4], uint32_t b0, uint32_t b1){
    asm volatile("mma.sync.aligned.m16n8k16.row.col.f32.f16.f16.f32 "
        "{%0,%1,%2,%3},{%4,%5,%6,%7},{%8,%9},{%0,%1,%2,%3};"
        : "+f"(c[0]), "+f"(c[1]), "+f"(c[2]), "+f"(c[3])
        : "r"(a[0]), "r"(a[1]), "r"(a[2]), "r"(a[3]), "r"(b0), "r"(b1));
}
__device__ __forceinline__ uint32_t pkh2(float a, float b){
    __half2 h = __floats2half2_rn(a, b);
    return reinterpret_cast<uint32_t&>(h);
}
__device__ __forceinline__ float siluf(float x){ return x / (1.f + __expf(-x)); }
// swizzles (relative byte offsets; conflict-free ldmatrix phases)
__device__ __forceinline__ uint32_t swA(uint32_t o){ return o ^ (((o >> 7) & 7) << 4); }   // 128B rows
__device__ __forceinline__ uint32_t sw256(uint32_t o){ return o ^ (((o >> 8) & 7) << 4); } // 256B rows

// ------- weight convert prepass: fp32[K,Ns] -> fp16 ------------------------
__device__ __forceinline__ void cvt8_body(const float* __restrict__ src, __half* __restrict__ dst,
                                          int Ns, int Nd, int col0, int total8){
    int idx = blockIdx.x*blockDim.x + threadIdx.x;
    if (idx >= total8) return;
    int ns8 = Ns >> 3;
    int k = idx / ns8, j = (idx - k*ns8) << 3;
    const float4* s = (const float4*)(src + (size_t)k*Ns + j);
    float4 v0 = s[0], v1 = s[1];
    uint4 o;
    o.x = pkh2(v0.x, v0.y); o.y = pkh2(v0.z, v0.w);
    o.z = pkh2(v1.x, v1.y); o.w = pkh2(v1.z, v1.w);
    *(uint4*)(dst + (size_t)k*Nd + j + col0) = o;
}

// qkv convert: 16 elems/thread, 2x uint4 stores (high MLP, critical path head)
__global__ void cvt_qkv(const float* wq, const float* wk, const float* wv, __half* dst){
    const float* srcs[3] = {wq, wk, wv};
    const float* src = srcs[blockIdx.y];
    int idx = blockIdx.x*blockDim.x + threadIdx.x;
    if (idx >= DM*DM/16) return;
    int ns16 = DM >> 4;
    int k = idx / ns16, j = (idx - k*ns16) << 4;
    const float4* s = (const float4*)(src + (size_t)k*DM + j);
    float4 v0 = s[0], v1 = s[1], v2 = s[2], v3 = s[3];
    uint4 o0, o1;
    o0.x = pkh2(v0.x,v0.y); o0.y = pkh2(v0.z,v0.w);
    o0.z = pkh2(v1.x,v1.y); o0.w = pkh2(v1.z,v1.w);
    o1.x = pkh2(v2.x,v2.y); o1.y = pkh2(v2.z,v2.w);
    o1.z = pkh2(v3.x,v3.y); o1.w = pkh2(v3.z,v3.w);
    __half* d = dst + (size_t)k*QKVN + blockIdx.y*DM + j;
    *(uint4*)(d)     = o0;
    *(uint4*)(d + 8) = o1;
}
// w1/w3 interleaved by 8 cols; contiguous 32B stores
__global__ void cvt_w13(const float* __restrict__ w1, const float* __restrict__ w3,
                        __half* __restrict__ dst){
    int idx = blockIdx.x*blockDim.x + threadIdx.x;
    const int total8 = DM*HID/8;
    if (idx >= total8) return;
    int ns8 = HID >> 3;
    int k = idx / ns8, j8 = idx - k*ns8;
    const float4* a = (const float4*)(w1 + (size_t)k*HID + j8*8);
    const float4* b = (const float4*)(w3 + (size_t)k*HID + j8*8);
    float4 a0 = a[0], a1 = a[1];
    float4 b0 = b[0], b1 = b[1];
    uint4 o1 = make_uint4(pkh2(a0.x,a0.y), pkh2(a0.z,a0.w), pkh2(a1.x,a1.y), pkh2(a1.z,a1.w));
    uint4 o3 = make_uint4(pkh2(b0.x,b0.y), pkh2(b0.z,b0.w), pkh2(b1.x,b1.y), pkh2(b1.z,b1.w));
    __half* d = dst + (size_t)k*FFN2 + j8*16;
    *(uint4*)(d)     = o1;
    *(uint4*)(d + 8) = o3;
}
__global__ void cvt_ow2(const float* wo, const float* w2, __half* dwo, __half* dw2){
    if (blockIdx.y == 0) cvt8_body(wo, dwo, DM, DM, 0, DM*DM/8);
    else                 cvt8_body(w2, dw2, DM, DM, 0, HID*DM/8);
}

// ---------------- rmsnorm (fp32 in -> fp16 out, vectorized) ----------------
__global__ void rmsnorm_kernel(const float* __restrict__ x, const float* __restrict__ w,
                               __half* __restrict__ out){
    int row = blockIdx.x;
    const float4* xr = (const float4*)(x + (size_t)row*DM);
    float4 v0 = xr[threadIdx.x], v1 = xr[threadIdx.x + 256];
    float ss = v0.x*v0.x + v0.y*v0.y + v0.z*v0.z + v0.w*v0.w
             + v1.x*v1.x + v1.y*v1.y + v1.z*v1.z + v1.w*v1.w;
    __shared__ float red[8];
    #pragma unroll
    for (int o = 16; o; o >>= 1) ss += __shfl_xor_sync(~0u, ss, o);
    if ((threadIdx.x & 31) == 0) red[threadIdx.x >> 5] = ss;
    __syncthreads();
    if (threadIdx.x == 0){
        float t = 0.f;
        #pragma unroll
        for (int i = 0; i < 8; i++) t += red[i];
        red[0] = t;
    }
    __syncthreads();
    float inv = rsqrtf(red[0] / (float)DM + 1e-5f);
    const float4* w4 = (const float4*)w;
    uint2* o2 = (uint2*)(out + (size_t)row*DM);
    float4 a = w4[threadIdx.x], b = w4[threadIdx.x + 256];
    o2[threadIdx.x]       = make_uint2(pkh2(v0.x*inv*a.x, v0.y*inv*a.y), pkh2(v0.z*inv*a.z, v0.w*inv*a.w));
    o2[threadIdx.x + 256] = make_uint2(pkh2(v1.x*inv*b.x, v1.y*inv*b.y), pkh2(v1.z*inv*b.z, v1.w*inv*b.w));
}

// ================= fp16 GEMM: C[M,N] = A[M,K] @ B[K,N] =====================
// 128x128 block, 4 warps of 64x64, BK=64, 3-stage cp.async, 2 CTAs/SM.
#define GSTG_BYTES (32*1024)
#define GEMM_SMEM  (3*GSTG_BYTES)     // 98304 -> 2 CTAs/SM
#define QSCALE 0.08838834764831845f   // 1/sqrt(128), folded into Q

template<bool ADD, bool HOUT, bool ROPE, bool SILU>
__global__ void __launch_bounds__(128, 2)
gemm_kernel(const __half* __restrict__ A, const __half* __restrict__ B,
            const float* __restrict__ Add, void* __restrict__ Cv,
            int M, int N, int K,
            const float* __restrict__ fc, const float* __restrict__ fs)
{
    extern __shared__ char smem[];
    const uint32_t sb = smem_u32(smem);
    const int tid = threadIdx.x, lane = tid & 31, wid = tid >> 5;   // 4 warps
    const int wm = (wid >> 1) * 64;
    const int wn = (wid & 1) * 64;
    const int bm = blockIdx.y * 128, bn = blockIdx.x * 128;

    float acc[4][8][4];
    #pragma unroll
    for (int i=0;i<4;i++)
        #pragma unroll
        for (int j=0;j<8;j++)
            #pragma unroll
            for (int r=0;r<4;r++) acc[i][j][r] = 0.f;

    const int nk = K / 64;

    auto issue = [&](int kt, int st){
        char* Ad = smem + st*GSTG_BYTES;
        const __half* Ag = A + (size_t)bm*K + kt*64;
        #pragma unroll
        for (int i = 0; i < 8; i++){
            int idx = tid + i*128;            // 0..1023
            int m = idx >> 3, c = idx & 7;
            cp16(Ad + swA(m*128 + c*16), Ag + (size_t)m*K + c*8);
        }
        char* Bd = Ad + 16*1024;
        const __half* Bg = B + (size_t)(kt*64)*N + bn;
        #pragma unroll
        for (int i = 0; i < 8; i++){
            int idx = tid + i*128;            // 0..1023
            int k = idx >> 4, c = idx & 15;
            cp16(Bd + sw256(k*256 + c*16), Bg + (size_t)k*N + c*8);
        }
        cp_commit();
    };

    issue(0, 0); issue(1, 1);
    int cur = 0, nxt = 2;
    for (int kt = 0; kt < nk; kt++){
        cp_wait1();
        __syncthreads();
        if (kt+2 < nk) issue(kt+2, nxt);
        const uint32_t sA = sb + cur*GSTG_BYTES;
        const uint32_t sB = sA + 16*1024;
        if (++cur == 3) cur = 0;
        if (++nxt == 3) nxt = 0;
        #pragma unroll
        for (int ks = 0; ks < 4; ks++){
            uint32_t af[4][4];
            #pragma unroll
            for (int mt = 0; mt < 4; mt++){
                int row = wm + mt*16 + (lane&7) + ((lane>>3)&1)*8;
                int ch  = 2*ks + (lane>>4);
                ldm4(af[mt], sA + swA(row*128 + ch*16));
            }
            uint32_t bf[4][4];
            #pragma unroll
            for (int ntp = 0; ntp < 4; ntp++){
                int krow = ks*16 + (lane&7) + ((lane>>3)&1)*8;
                int ch   = ((wn + ntp*16) >> 3) + (lane>>4);
                ldm4t(bf[ntp], sB + sw256(krow*256 + ch*16));
            }
            #pragma unroll
            for (int mt = 0; mt < 4; mt++)
                #pragma unroll
                for (int ntp = 0; ntp < 4; ntp++){
                    mma_f16(acc[mt][2*ntp],   af[mt], bf[ntp][0], bf[ntp][1]);
                    mma_f16(acc[mt][2*ntp+1], af[mt], bf[ntp][2], bf[ntp][3]);
                }
        }
    }

    // ---------------- epilogue ----------------
    if (SILU){
        __half* C = (__half*)Cv;
        const int NO = N >> 1;    // HID
        #pragma unroll
        for (int mt = 0; mt < 4; mt++){
            int r0 = bm + wm + mt*16 + (lane>>2);
            #pragma unroll
            for (int ntp = 0; ntp < 4; ntp++){
                int j = ((bn + wn) >> 1) + ntp*8 + (lane&3)*2;
                const float* a1 = acc[mt][2*ntp];
                const float* a3 = acc[mt][2*ntp+1];
                *(uint32_t*)(C + (size_t)r0*NO + j) =
                    pkh2(siluf(a1[0])*a3[0], siluf(a1[1])*a3[1]);
                *(uint32_t*)(C + (size_t)(r0+8)*NO + j) =
                    pkh2(siluf(a1[2])*a3[2], siluf(a1[3])*a3[3]);
            }
        }
        return;
    }
    #pragma unroll
    for (int mt = 0; mt < 4; mt++){
        #pragma unroll
        for (int nt = 0; nt < 8; nt++){
            int r = bm + wm + mt*16 + (lane>>2);
            int c = bn + wn + nt*8 + (lane&3)*2;
            float2 v0 = make_float2(acc[mt][nt][0], acc[mt][nt][1]);
            float2 v1 = make_float2(acc[mt][nt][2], acc[mt][nt][3]);
            if (ADD){
                const float* A0 = Add + (size_t)r*N + c;
                const float* A1 = Add + (size_t)(r+8)*N + c;
                v0.x += A0[0]; v0.y += A0[1];
                v1.x += A1[0]; v1.y += A1[1];
            }
            if (ROPE && c < 2*DM){
                int i = (c & (HDIM-1)) >> 1;
                int s0 = r & (SEQ-1), s1 = (r+8) & (SEQ-1);
                float c0 = fc[s0*64 + i], sn0 = fs[s0*64 + i];
                float c1 = fc[s1*64 + i], sn1 = fs[s1*64 + i];
                float a = v0.x, b = v0.y;
                v0.x = a*c0 - b*sn0; v0.y = a*sn0 + b*c0;
                a = v1.x; b = v1.y;
                v1.x = a*c1 - b*sn1; v1.y = a*sn1 + b*c1;
                if (c < DM){   // q slice: fold softmax scale
                    v0.x *= QSCALE; v0.y *= QSCALE;
                    v1.x *= QSCALE; v1.y *= QSCALE;
                }
            }
            if (HOUT){
                __half* C = (__half*)Cv;
                *(uint32_t*)(C + (size_t)r*N + c)     = pkh2(v0.x, v0.y);
                *(uint32_t*)(C + (size_t)(r+8)*N + c) = pkh2(v1.x, v1.y);
            } else {
                float* C = (float*)Cv;
                *(float2*)(C + (size_t)r*N + c)     = v0;
                *(float2*)(C + (size_t)(r+8)*N + c) = v1;
            }
        }
    }
}

// ---------------- flash attention, BQ=128, 256 threads, P in registers -----
// Two-stage KV double buffer (R13 structure) + rescale-skip softmax.
#define FQ_OFF  0
#define FK_OFF  (32*1024)
#define FV_OFF  (64*1024)
#define FLASH_SMEM (96*1024)

__global__ void __launch_bounds__(256)
flash_kernel(const __half* __restrict__ QKV, __half* __restrict__ O)
{
    extern __shared__ char smem[];
    const uint32_t sb = smem_u32(smem);
    const int tid = threadIdx.x, lane = tid & 31, wid = tid >> 5;
    const int qt = blockIdx.x, h = blockIdx.y;
    const int q0 = qt*128;

    {   // Q: 128 rows x 256B (pre-scaled by 1/sqrt(HD) in QKV epilogue)
        const __half* Qg = QKV + (size_t)q0*QKVN + h*HDIM;
        #pragma unroll
        for (int i = 0; i < 8; i++){
            int idx = tid + i*256;
            int r = idx >> 4, c = idx & 15;
            cp16(smem + FQ_OFF + sw256(r*256 + c*16), Qg + (size_t)r*QKVN + c*8);
        }
    }
    auto issueKV = [&](int kt, int st){
        const __half* Kg = QKV + (size_t)(kt*64)*QKVN + DM   + h*HDIM;
        const __half* Vg = QKV + (size_t)(kt*64)*QKVN + 2*DM + h*HDIM;
        char* Kd = smem + FK_OFF + st*16*1024;
        char* Vd = smem + FV_OFF + st*16*1024;
        #pragma unroll
        for (int i = 0; i < 4; i++){
            int idx = tid + i*256;
            int r = idx >> 4, c = idx & 15;
            uint32_t so = sw256(r*256 + c*16);
            cp16(Kd + so, Kg + (size_t)r*QKVN + c*8);
            cp16(Vd + so, Vg + (size_t)r*QKVN + c*8);
        }
        cp_commit();
    };
    issueKV(0, 0);
    cp_wait0();
    __syncthreads();

    uint32_t qf[8][4];
    #pragma unroll
    for (int ks = 0; ks < 8; ks++){
        int row = wid*16 + (lane&7) + ((lane>>3)&1)*8;
        int ch  = 2*ks + (lane>>4);
        ldm4(qf[ks], sb + FQ_OFF + sw256(row*256 + ch*16));
    }

    float m0 = -1e30f, m1 = -1e30f, l0 = 0.f, l1 = 0.f;
    float oacc[16][4];
    #pragma unroll
    for (int i=0;i<16;i++)
        #pragma unroll
        for (int j=0;j<4;j++) oacc[i][j] = 0.f;

    const int nkt = SEQ / 64;     // 32
    for (int kt = 0; kt < nkt; kt++){
        if (kt > 0){ cp_wait0(); __syncthreads(); }
        if (kt+1 < nkt) issueKV(kt+1, (kt+1)&1);
        const uint32_t sK = sb + FK_OFF + (kt&1)*16*1024;
        const uint32_t sV = sb + FV_OFF + (kt&1)*16*1024;

        float sacc[8][4];
        #pragma unroll
        for (int i=0;i<8;i++)
            #pragma unroll
            for (int j=0;j<4;j++) sacc[i][j] = 0.f;
        #pragma unroll
        for (int ks = 0; ks < 8; ks++){
            #pragma unroll
            for (int ntp = 0; ntp < 4; ntp++){
                uint32_t kf[4];
                int row = ntp*16 + ((lane>>4)&1)*8 + (lane&7);
                int ch  = 2*ks + ((lane>>3)&1);
                ldm4(kf, sK + sw256(row*256 + ch*16));
                mma_f16(sacc[2*ntp],   qf[ks], kf[0], kf[1]);
                mma_f16(sacc[2*ntp+1], qf[ks], kf[2], kf[3]);
            }
        }

        float mx0 = -1e30f, mx1 = -1e30f;
        #pragma unroll
        for (int nt=0; nt<8; nt++){
            mx0 = fmaxf(mx0, fmaxf(sacc[nt][0], sacc[nt][1]));
            mx1 = fmaxf(mx1, fmaxf(sacc[nt][2], sacc[nt][3]));
        }
        mx0 = fmaxf(mx0, __shfl_xor_sync(~0u, mx0, 1));
        mx0 = fmaxf(mx0, __shfl_xor_sync(~0u, mx0, 2));
        mx1 = fmaxf(mx1, __shfl_xor_sync(~0u, mx1, 1));
        mx1 = fmaxf(mx1, __shfl_xor_sync(~0u, mx1, 2));
        float mn0 = fmaxf(m0, mx0), mn1 = fmaxf(m1, mx1);
        bool chg = (mn0 > m0) || (mn1 > m1);
        float rs0 = 0.f, rs1 = 0.f;
        #pragma unroll
        for (int nt=0; nt<8; nt++){
            sacc[nt][0] = __expf(sacc[nt][0] - mn0);
            sacc[nt][1] = __expf(sacc[nt][1] - mn0);
            sacc[nt][2] = __expf(sacc[nt][2] - mn1);
            sacc[nt][3] = __expf(sacc[nt][3] - mn1);
            rs0 += sacc[nt][0] + sacc[nt][1];
            rs1 += sacc[nt][2] + sacc[nt][3];
        }
        rs0 += __shfl_xor_sync(~0u, rs0, 1); rs0 += __shfl_xor_sync(~0u, rs0, 2);
        rs1 += __shfl_xor_sync(~0u, rs1, 1); rs1 += __shfl_xor_sync(~0u, rs1, 2);
        if (chg){
            float cr0 = __expf(m0 - mn0), cr1 = __expf(m1 - mn1);
            l0 = l0*cr0 + rs0; l1 = l1*cr1 + rs1;
            #pragma unroll
            for (int i=0;i<16;i++){
                oacc[i][0] *= cr0; oacc[i][1] *= cr0;
                oacc[i][2] *= cr1; oacc[i][3] *= cr1;
            }
            m0 = mn0; m1 = mn1;
        } else {
            l0 += rs0; l1 += rs1;
        }

        #pragma unroll
        for (int kv = 0; kv < 4; kv++){
            uint32_t pf[4];
            pf[0] = pkh2(sacc[2*kv][0],   sacc[2*kv][1]);
            pf[1] = pkh2(sacc[2*kv][2],   sacc[2*kv][3]);
            pf[2] = pkh2(sacc[2*kv+1][0], sacc[2*kv+1][1]);
            pf[3] = pkh2(sacc[2*kv+1][2], sacc[2*kv+1][3]);
            #pragma unroll
            for (int ntp = 0; ntp < 8; ntp++){
                uint32_t vf[4];
                int row = kv*16 + (lane&7) + ((lane>>3)&1)*8;
                int ch  = 2*ntp + (lane>>4);
                ldm4t(vf, sV + sw256(row*256 + ch*16));
                mma_f16(oacc[2*ntp],   pf, vf[0], vf[1]);
                mma_f16(oacc[2*ntp+1], pf, vf[2], vf[3]);
            }
        }
    }

    float inv0 = 1.f/l0, inv1 = 1.f/l1;
    int r = wid*16 + (lane>>2);
    __half* Og0 = O + ((size_t)(q0 + r))*DM + h*HDIM;
    __half* Og1 = O + ((size_t)(q0 + r + 8))*DM + h*HDIM;
    #pragma unroll
    for (int nt=0; nt<16; nt++){
        int c = nt*8 + (lane&3)*2;
        *(uint32_t*)(Og0 + c) = pkh2(oacc[nt][0]*inv0, oacc[nt][1]*inv0);
        *(uint32_t*)(Og1 + c) = pkh2(oacc[nt][2]*inv1, oacc[nt][3]*inv1);
    }
}

// ---------------- launch: 3-stream pipeline (split weight-ready events) -----
extern "C" void kernel_launch(void* const* d_in, const int* in_sizes, int n_in,
                              void* d_out, int out_size){
    const float* x   = (const float*)d_in[0];
    const float* fc  = (const float*)d_in[1];
    const float* fs  = (const float*)d_in[2];
    const float* wq  = (const float*)d_in[3];
    const float* wk  = (const float*)d_in[4];
    const float* wv  = (const float*)d_in[5];
    const float* wo  = (const float*)d_in[6];
    const float* w1  = (const float*)d_in[7];
    const float* w2  = (const float*)d_in[8];
    const float* w3  = (const float*)d_in[9];
    const float* anw = (const float*)d_in[10];
    const float* fnw = (const float*)d_in[11];
    float* out = (float*)d_out;

    __half *xn,*qkv,*attn,*hn,*ffa,*wqkvH,*woH,*w13H,*w2H;
    float  *h;
    cudaGetSymbolAddress((void**)&xn,    g_xn);
    cudaGetSymbolAddress((void**)&qkv,   g_qkv);
    cudaGetSymbolAddress((void**)&attn,  g_attn);
    cudaGetSymbolAddress((void**)&h,     g_h);
    cudaGetSymbolAddress((void**)&hn,    g_hn);
    cudaGetSymbolAddress((void**)&ffa,   g_ffa);
    cudaGetSymbolAddress((void**)&wqkvH, g_wqkv);
    cudaGetSymbolAddress((void**)&woH,   g_wo);
    cudaGetSymbolAddress((void**)&w13H,  g_w13);
    cudaGetSymbolAddress((void**)&w2H,   g_w2);

    cudaFuncSetAttribute((const void*)gemm_kernel<false,true,true,false>,  cudaFuncAttributeMaxDynamicSharedMemorySize, GEMM_SMEM);
    cudaFuncSetAttribute((const void*)gemm_kernel<true,false,false,false>, cudaFuncAttributeMaxDynamicSharedMemorySize, GEMM_SMEM);
    cudaFuncSetAttribute((const void*)gemm_kernel<false,true,false,true>,  cudaFuncAttributeMaxDynamicSharedMemorySize, GEMM_SMEM);
    cudaFuncSetAttribute((const void*)flash_kernel, cudaFuncAttributeMaxDynamicSharedMemorySize, FLASH_SMEM);

    const int thr = 256;
    const int t16 = DM*DM/16;     // 262144 (qkv 16-elem chunks)
    const int t8p = DM*HID/8;     // 1441792
    dim3 gq(QKVN/128, HTOK/128);  // (48,16)
    dim3 gd(DM/128,  HTOK/128);   // (16,16)
    dim3 gffh(FFN2/128, HTOK/128);// (88,16)
    dim3 gfl(SEQ/128, NH, 1);     // (16,16,1)

    // fork all three pipelines off the capture stream
    cudaEventRecord(g_e0, 0);
    cudaStreamWaitEvent(g_s1, g_e0, 0);
    cudaStreamWaitEvent(g_s2, g_e0, 0);
    cudaStreamWaitEvent(g_s3, g_e0, 0);

    // s3: weight converts in dependency order: qkv -> ow2 -> w13.
    cvt_qkv<<<dim3((t16+thr-1)/thr, 3), thr, 0, g_s3>>>(wq, wk, wv, wqkvH);
    cudaEventRecord(g_eQ, g_s3);
    cvt_ow2<<<dim3((t8p+thr-1)/thr, 2), thr, 0, g_s3>>>(wo, w2, woH, w2H);
    cudaEventRecord(g_eW, g_s3);
    cvt_w13<<<(t8p+thr-1)/thr, thr, 0, g_s3>>>(w1, w3, w13H);
    cudaEventRecord(g_eF, g_s3);

    // ---- stream 1: batch 0 (rows 0..2047) ----
    {
        const size_t r0 = 0;
        rmsnorm_kernel<<<HTOK, 256, 0, g_s1>>>(x + r0*DM, anw, xn + r0*DM);
        cudaStreamWaitEvent(g_s1, g_eQ, 0);
        gemm_kernel<false,true,true,false><<<gq, 128, GEMM_SMEM, g_s1>>>(
            xn + r0*DM, wqkvH, nullptr, qkv + r0*QKVN, HTOK, QKVN, DM, fc, fs);
        flash_kernel<<<gfl, 256, FLASH_SMEM, g_s1>>>(qkv + r0*QKVN, attn + r0*DM);
        cudaStreamWaitEvent(g_s1, g_eW, 0);
        gemm_kernel<true,false,false,false><<<gd, 128, GEMM_SMEM, g_s1>>>(
            attn + r0*DM, woH, x + r0*DM, h + r0*DM, HTOK, DM, DM, nullptr, nullptr);
        rmsnorm_kernel<<<HTOK, 256, 0, g_s1>>>(h + r0*DM, fnw, hn + r0*DM);
        cudaStreamWaitEvent(g_s1, g_eF, 0);
        gemm_kernel<false,true,false,true><<<gffh, 128, GEMM_SMEM, g_s1>>>(
            hn + r0*DM, w13H, nullptr, ffa + r0*HID, HTOK, FFN2, DM, nullptr, nullptr);
        gemm_kernel<true,false,false,false><<<gd, 128, GEMM_SMEM, g_s1>>>(
            ffa + r0*HID, w2H, h + r0*DM, out + r0*DM, HTOK, DM, HID, nullptr, nullptr);
        cudaEventRecord(g_e1, g_s1);
    }

    // ---- stream 2: batch 1 (rows 2048..4095) ----
    {
        const size_t r0 = HTOK;
        rmsnorm_kernel<<<HTOK, 256, 0, g_s2>>>(x + r0*DM, anw, xn + r0*DM);
        cudaStreamWaitEvent(g_s2, g_eQ, 0);
        gemm_kernel<false,true,true,false><<<gq, 128, GEMM_SMEM, g_s2>>>(
            xn + r0*DM, wqkvH, nullptr, qkv + r0*QKVN, HTOK, QKVN, DM, fc, fs);
        flash_kernel<<<gfl, 256, FLASH_SMEM, g_s2>>>(qkv + r0*QKVN, attn + r0*DM);
        cudaStreamWaitEvent(g_s2, g_eW, 0);
        gemm_kernel<true,false,false,false><<<gd, 128, GEMM_SMEM, g_s2>>>(
            attn + r0*DM, woH, x + r0*DM, h + r0*DM, HTOK, DM, DM, nullptr, nullptr);
        rmsnorm_kernel<<<HTOK, 256, 0, g_s2>>>(h + r0*DM, fnw, hn + r0*DM);
        cudaStreamWaitEvent(g_s2, g_eF, 0);
        gemm_kernel<false,true,false,true><<<gffh, 128, GEMM_SMEM, g_s2>>>(
            hn + r0*DM, w13H, nullptr, ffa + r0*HID, HTOK, FFN2, DM, nullptr, nullptr);
        gemm_kernel<true,false,false,false><<<gd, 128, GEMM_SMEM, g_s2>>>(
            ffa + r0*HID, w2H, h + r0*DM, out + r0*DM, HTOK, DM, HID, nullptr, nullptr);
        cudaEventRecord(g_e2, g_s2);
    }

    // join back to the capture stream
    cudaStreamWaitEvent(0, g_e1, 0);
    cudaStreamWaitEvent(0, g_e2, 0);
}

// round 16
// speedup vs baseline: 1.0200x; 1.0194x over previous
#include <cuda_runtime.h>
#include <cuda_fp16.h>
#include <math.h>
#include <stdint.h>

#define BSZ   2
#define SEQ   2048
#define DM    2048
#define NH    16
#define HDIM  128
#define HID   5632
#define NTOK  (BSZ*SEQ)     // 4096
#define HTOK  (NTOK/2)      // 2048 rows per batch half
#define QKVN  (3*DM)        // 6144
#define FFN2  (2*HID)       // 11264

// ---------------- scratch (no allocation allowed -> __device__ globals) ----
__device__ __half g_xn  [NTOK*(size_t)DM];
__device__ __half g_qkv [NTOK*(size_t)QKVN];
__device__ __half g_attn[NTOK*(size_t)DM];
__device__ float  g_h   [NTOK*(size_t)DM];
__device__ __half g_hn  [NTOK*(size_t)DM];
__device__ __half g_ffa [NTOK*(size_t)HID];
// fp16 weights, [K,N] layout (wq|wk|wv fused; w1/w3 interleaved by 8 cols)
__device__ __half g_wqkv[DM*(size_t)QKVN];
__device__ __half g_wo  [DM*(size_t)DM];
__device__ __half g_w13 [DM*(size_t)FFN2];
__device__ __half g_w2  [HID*(size_t)DM];

// ---------------- streams/events created at static init (pre-checkpoint) ---
static cudaStream_t g_s1, g_s2, g_s3;
static cudaEvent_t  g_e0, g_eQ, g_eW, g_eF, g_e1, g_e2;
static struct StreamInit {
    StreamInit(){
        cudaStreamCreateWithFlags(&g_s1, cudaStreamNonBlocking);
        cudaStreamCreateWithFlags(&g_s2, cudaStreamNonBlocking);
        cudaStreamCreateWithFlags(&g_s3, cudaStreamNonBlocking);
        cudaEventCreateWithFlags(&g_e0, cudaEventDisableTiming);
        cudaEventCreateWithFlags(&g_eQ, cudaEventDisableTiming);
        cudaEventCreateWithFlags(&g_eW, cudaEventDisableTiming);
        cudaEventCreateWithFlags(&g_eF, cudaEventDisableTiming);
        cudaEventCreateWithFlags(&g_e1, cudaEventDisableTiming);
        cudaEventCreateWithFlags(&g_e2, cudaEventDisableTiming);
    }
} g_stream_init;

// ---------------- helpers --------------------------------------------------
__device__ __forceinline__ uint32_t smem_u32(const void* p){
    uint32_t a;
    asm("{ .reg .u64 t; cvta.to.shared.u64 t, %1; cvt.u32.u64 %0, t; }" : "=r"(a) : "l"(p));
    return a;
}
__device__ __forceinline__ void cp16(void* dst, const void* src){
    unsigned d = (unsigned)__cvta_generic_to_shared(dst);
    asm volatile("cp.async.cg.shared.global [%0], [%1], 16;" :: "r"(d), "l"(src));
}
__device__ __forceinline__ void cp_commit(){ asm volatile("cp.async.commit_group;"); }
__device__ __forceinline__ void cp_wait0(){ asm volatile("cp.async.wait_group 0;"); }
__device__ __forceinline__ void cp_wait1(){ asm volatile("cp.async.wait_group 1;"); }

__device__ __forceinline__ void ldm4(uint32_t r[4], uint32_t addr){
    asm volatile("ldmatrix.sync.aligned.m8n8.x4.shared.b16 {%0,%1,%2,%3}, [%4];"
        : "=r"(r[0]), "=r"(r[1]), "=r"(r[2]), "=r"(r[3]) : "r"(addr));
}
__device__ __forceinline__ void ldm4t(uint32_t r[4], uint32_t addr){
    asm volatile("ldmatrix.sync.aligned.m8n8.x4.trans.shared.b16 {%0,%1,%2,%3}, [%4];"
        : "=r"(r[0]), "=r"(r[1]), "=r"(r[2]), "=r"(r[3]) : "r"(addr));
}
__device__ __forceinline__ void mma_f16(float c[4], const uint32_t a[4], uint32_t b0, uint32_t b1){
    asm volatile("mma.sync.aligned.m16n8k16.row.col.f32.f16.f16.f32 "
        "{%0,%1,%2,%3},{%4,%5,%6,%7},{%8,%9},{%0,%1,%2,%3};"
        : "+f"(c[0]), "+f"(c[1]), "+f"(c[2]), "+f"(c[3])
        : "r"(a[0]), "r"(a[1]), "r"(a[2]), "r"(a[3]), "r"(b0), "r"(b1));
}
__device__ __forceinline__ uint32_t pkh2(float a, float b){
    __half2 h = __floats2half2_rn(a, b);
    return reinterpret_cast<uint32_t&>(h);
}
__device__ __forceinline__ float siluf(float x){ return x / (1.f + __expf(-x)); }
// swizzles (relative byte offsets; conflict-free ldmatrix phases)
__device__ __forceinline__ uint32_t swA(uint32_t o){ return o ^ (((o >> 7) & 7) << 4); }   // 128B rows
__device__ __forceinline__ uint32_t sw256(uint32_t o){ return o ^ (((o >> 8) & 7) << 4); } // 256B rows

// ------- weight convert prepass: fp32[K,Ns] -> fp16 ------------------------
__device__ __forceinline__ void cvt8_body(const float* __restrict__ src, __half* __restrict__ dst,
                                          int Ns, int Nd, int col0, int total8){
    int idx = blockIdx.x*blockDim.x + threadIdx.x;
    if (idx >= total8) return;
    int ns8 = Ns >> 3;
    int k = idx / ns8, j = (idx - k*ns8) << 3;
    const float4* s = (const float4*)(src + (size_t)k*Ns + j);
    float4 v0 = s[0], v1 = s[1];
    uint4 o;
    o.x = pkh2(v0.x, v0.y); o.y = pkh2(v0.z, v0.w);
    o.z = pkh2(v1.x, v1.y); o.w = pkh2(v1.z, v1.w);
    *(uint4*)(dst + (size_t)k*Nd + j + col0) = o;
}

// qkv convert: 16 elems/thread, 2x uint4 stores (high MLP, critical path head)
__global__ void cvt_qkv(const float* wq, const float* wk, const float* wv, __half* dst){
    const float* srcs[3] = {wq, wk, wv};
    const float* src = srcs[blockIdx.y];
    int idx = blockIdx.x*blockDim.x + threadIdx.x;
    if (idx >= DM*DM/16) return;
    int ns16 = DM >> 4;
    int k = idx / ns16, j = (idx - k*ns16) << 4;
    const float4* s = (const float4*)(src + (size_t)k*DM + j);
    float4 v0 = s[0], v1 = s[1], v2 = s[2], v3 = s[3];
    uint4 o0, o1;
    o0.x = pkh2(v0.x,v0.y); o0.y = pkh2(v0.z,v0.w);
    o0.z = pkh2(v1.x,v1.y); o0.w = pkh2(v1.z,v1.w);
    o1.x = pkh2(v2.x,v2.y); o1.y = pkh2(v2.z,v2.w);
    o1.z = pkh2(v3.x,v3.y); o1.w = pkh2(v3.z,v3.w);
    __half* d = dst + (size_t)k*QKVN + blockIdx.y*DM + j;
    *(uint4*)(d)     = o0;
    *(uint4*)(d + 8) = o1;
}
// w1/w3 interleaved by 8 cols; contiguous 32B stores
__global__ void cvt_w13(const float* __restrict__ w1, const float* __restrict__ w3,
                        __half* __restrict__ dst){
    int idx = blockIdx.x*blockDim.x + threadIdx.x;
    const int total8 = DM*HID/8;
    if (idx >= total8) return;
    int ns8 = HID >> 3;
    int k = idx / ns8, j8 = idx - k*ns8;
    const float4* a = (const float4*)(w1 + (size_t)k*HID + j8*8);
    const float4* b = (const float4*)(w3 + (size_t)k*HID + j8*8);
    float4 a0 = a[0], a1 = a[1];
    float4 b0 = b[0], b1 = b[1];
    uint4 o1 = make_uint4(pkh2(a0.x,a0.y), pkh2(a0.z,a0.w), pkh2(a1.x,a1.y), pkh2(a1.z,a1.w));
    uint4 o3 = make_uint4(pkh2(b0.x,b0.y), pkh2(b0.z,b0.w), pkh2(b1.x,b1.y), pkh2(b1.z,b1.w));
    __half* d = dst + (size_t)k*FFN2 + j8*16;
    *(uint4*)(d)     = o1;
    *(uint4*)(d + 8) = o3;
}
__global__ void cvt_ow2(const float* wo, const float* w2, __half* dwo, __half* dw2){
    if (blockIdx.y == 0) cvt8_body(wo, dwo, DM, DM, 0, DM*DM/8);
    else                 cvt8_body(w2, dw2, DM, DM, 0, HID*DM/8);
}

// ---------------- rmsnorm (fp32 in -> fp16 out, vectorized) ----------------
__global__ void rmsnorm_kernel(const float* __restrict__ x, const float* __restrict__ w,
                               __half* __restrict__ out){
    int row = blockIdx.x;
    const float4* xr = (const float4*)(x + (size_t)row*DM);
    float4 v0 = xr[threadIdx.x], v1 = xr[threadIdx.x + 256];
    float ss = v0.x*v0.x + v0.y*v0.y + v0.z*v0.z + v0.w*v0.w
             + v1.x*v1.x + v1.y*v1.y + v1.z*v1.z + v1.w*v1.w;
    __shared__ float red[8];
    #pragma unroll
    for (int o = 16; o; o >>= 1) ss += __shfl_xor_sync(~0u, ss, o);
    if ((threadIdx.x & 31) == 0) red[threadIdx.x >> 5] = ss;
    __syncthreads();
    if (threadIdx.x == 0){
        float t = 0.f;
        #pragma unroll
        for (int i = 0; i < 8; i++) t += red[i];
        red[0] = t;
    }
    __syncthreads();
    float inv = rsqrtf(red[0] / (float)DM + 1e-5f);
    const float4* w4 = (const float4*)w;
    uint2* o2 = (uint2*)(out + (size_t)row*DM);
    float4 a = w4[threadIdx.x], b = w4[threadIdx.x + 256];
    o2[threadIdx.x]       = make_uint2(pkh2(v0.x*inv*a.x, v0.y*inv*a.y), pkh2(v0.z*inv*a.z, v0.w*inv*a.w));
    o2[threadIdx.x + 256] = make_uint2(pkh2(v1.x*inv*b.x, v1.y*inv*b.y), pkh2(v1.z*inv*b.z, v1.w*inv*b.w));
}

// ================= fp16 GEMM: C[M,N] = A[M,K] @ B[K,N] =====================
// 128x128 block, 4 warps of 64x64, BK=64, 3-stage cp.async, 2 CTAs/SM.
#define GSTG_BYTES (32*1024)
#define GEMM_SMEM  (3*GSTG_BYTES)     // 98304 -> 2 CTAs/SM
#define QSCALE 0.08838834764831845f   // 1/sqrt(128), folded into Q

template<bool ADD, bool HOUT, bool ROPE, bool SILU>
__global__ void __launch_bounds__(128, 2)
gemm_kernel(const __half* __restrict__ A, const __half* __restrict__ B,
            const float* __restrict__ Add, void* __restrict__ Cv,
            int M, int N, int K,
            const float* __restrict__ fc, const float* __restrict__ fs)
{
    extern __shared__ char smem[];
    const uint32_t sb = smem_u32(smem);
    const int tid = threadIdx.x, lane = tid & 31, wid = tid >> 5;   // 4 warps
    const int wm = (wid >> 1) * 64;
    const int wn = (wid & 1) * 64;
    const int bm = blockIdx.y * 128, bn = blockIdx.x * 128;

    float acc[4][8][4];
    #pragma unroll
    for (int i=0;i<4;i++)
        #pragma unroll
        for (int j=0;j<8;j++)
            #pragma unroll
            for (int r=0;r<4;r++) acc[i][j][r] = 0.f;

    const int nk = K / 64;

    auto issue = [&](int kt, int st){
        char* Ad = smem + st*GSTG_BYTES;
        const __half* Ag = A + (size_t)bm*K + kt*64;
        #pragma unroll
        for (int i = 0; i < 8; i++){
            int idx = tid + i*128;            // 0..1023
            int m = idx >> 3, c = idx & 7;
            cp16(Ad + swA(m*128 + c*16), Ag + (size_t)m*K + c*8);
        }
        char* Bd = Ad + 16*1024;
        const __half* Bg = B + (size_t)(kt*64)*N + bn;
        #pragma unroll
        for (int i = 0; i < 8; i++){
            int idx = tid + i*128;            // 0..1023
            int k = idx >> 4, c = idx & 15;
            cp16(Bd + sw256(k*256 + c*16), Bg + (size_t)k*N + c*8);
        }
        cp_commit();
    };

    issue(0, 0); issue(1, 1);
    int cur = 0, nxt = 2;
    for (int kt = 0; kt < nk; kt++){
        cp_wait1();
        __syncthreads();
        if (kt+2 < nk) issue(kt+2, nxt);
        const uint32_t sA = sb + cur*GSTG_BYTES;
        const uint32_t sB = sA + 16*1024;
        if (++cur == 3) cur = 0;
        if (++nxt == 3) nxt = 0;
        #pragma unroll
        for (int ks = 0; ks < 4; ks++){
            uint32_t af[4][4];
            #pragma unroll
            for (int mt = 0; mt < 4; mt++){
                int row = wm + mt*16 + (lane&7) + ((lane>>3)&1)*8;
                int ch  = 2*ks + (lane>>4);
                ldm4(af[mt], sA + swA(row*128 + ch*16));
            }
            uint32_t bf[4][4];
            #pragma unroll
            for (int ntp = 0; ntp < 4; ntp++){
                int krow = ks*16 + (lane&7) + ((lane>>3)&1)*8;
                int ch   = ((wn + ntp*16) >> 3) + (lane>>4);
                ldm4t(bf[ntp], sB + sw256(krow*256 + ch*16));
            }
            #pragma unroll
            for (int mt = 0; mt < 4; mt++)
                #pragma unroll
                for (int ntp = 0; ntp < 4; ntp++){
                    mma_f16(acc[mt][2*ntp],   af[mt], bf[ntp][0], bf[ntp][1]);
                    mma_f16(acc[mt][2*ntp+1], af[mt], bf[ntp][2], bf[ntp][3]);
                }
        }
    }

    // ---------------- epilogue ----------------
    if (SILU){
        __half* C = (__half*)Cv;
        const int NO = N >> 1;    // HID
        #pragma unroll
        for (int mt = 0; mt < 4; mt++){
            int r0 = bm + wm + mt*16 + (lane>>2);
            #pragma unroll
            for (int ntp = 0; ntp < 4; ntp++){
                int j = ((bn + wn) >> 1) + ntp*8 + (lane&3)*2;
                const float* a1 = acc[mt][2*ntp];
                const float* a3 = acc[mt][2*ntp+1];
                *(uint32_t*)(C + (size_t)r0*NO + j) =
                    pkh2(siluf(a1[0])*a3[0], siluf(a1[1])*a3[1]);
                *(uint32_t*)(C + (size_t)(r0+8)*NO + j) =
                    pkh2(siluf(a1[2])*a3[2], siluf(a1[3])*a3[3]);
            }
        }
        return;
    }
    #pragma unroll
    for (int mt = 0; mt < 4; mt++){
        #pragma unroll
        for (int nt = 0; nt < 8; nt++){
            int r = bm + wm + mt*16 + (lane>>2);
            int c = bn + wn + nt*8 + (lane&3)*2;
            float2 v0 = make_float2(acc[mt][nt][0], acc[mt][nt][1]);
            float2 v1 = make_float2(acc[mt][nt][2], acc[mt][nt][3]);
            if (ADD){
                const float* A0 = Add + (size_t)r*N + c;
                const float* A1 = Add + (size_t)(r+8)*N + c;
                v0.x += A0[0]; v0.y += A0[1];
                v1.x += A1[0]; v1.y += A1[1];
            }
            if (ROPE && c < 2*DM){
                int i = (c & (HDIM-1)) >> 1;
                int s0 = r & (SEQ-1), s1 = (r+8) & (SEQ-1);
                float c0 = fc[s0*64 + i], sn0 = fs[s0*64 + i];
                float c1 = fc[s1*64 + i], sn1 = fs[s1*64 + i];
                float a = v0.x, b = v0.y;
                v0.x = a*c0 - b*sn0; v0.y = a*sn0 + b*c0;
                a = v1.x; b = v1.y;
                v1.x = a*c1 - b*sn1; v1.y = a*sn1 + b*c1;
                if (c < DM){   // q slice: fold softmax scale
                    v0.x *= QSCALE; v0.y *= QSCALE;
                    v1.x *= QSCALE; v1.y *= QSCALE;
                }
            }
            if (HOUT){
                __half* C = (__half*)Cv;
                *(uint32_t*)(C + (size_t)r*N + c)     = pkh2(v0.x, v0.y);
                *(uint32_t*)(C + (size_t)(r+8)*N + c) = pkh2(v1.x, v1.y);
            } else {
                float* C = (float*)Cv;
                *(float2*)(C + (size_t)r*N + c)     = v0;
                *(float2*)(C + (size_t)(r+8)*N + c) = v1;
            }
        }
    }
}

// ---------------- flash attention, BQ=128, 256 threads, P in registers -----
// Two-stage KV double buffer, unconditional online-softmax rescale.
#define FQ_OFF  0
#define FK_OFF  (32*1024)
#define FV_OFF  (64*1024)
#define FLASH_SMEM (96*1024)

__global__ void __launch_bounds__(256)
flash_kernel(const __half* __restrict__ QKV, __half* __restrict__ O)
{
    extern __shared__ char smem[];
    const uint32_t sb = smem_u32(smem);
    const int tid = threadIdx.x, lane = tid & 31, wid = tid >> 5;
    const int qt = blockIdx.x, h = blockIdx.y;
    const int q0 = qt*128;

    {   // Q: 128 rows x 256B (pre-scaled by 1/sqrt(HD) in QKV epilogue)
        const __half* Qg = QKV + (size_t)q0*QKVN + h*HDIM;
        #pragma unroll
        for (int i = 0; i < 8; i++){
            int idx = tid + i*256;
            int r = idx >> 4, c = idx & 15;
            cp16(smem + FQ_OFF + sw256(r*256 + c*16), Qg + (size_t)r*QKVN + c*8);
        }
    }
    auto issueKV = [&](int kt, int st){
        const __half* Kg = QKV + (size_t)(kt*64)*QKVN + DM   + h*HDIM;
        const __half* Vg = QKV + (size_t)(kt*64)*QKVN + 2*DM + h*HDIM;
        char* Kd = smem + FK_OFF + st*16*1024;
        char* Vd = smem + FV_OFF + st*16*1024;
        #pragma unroll
        for (int i = 0; i < 4; i++){
            int idx = tid + i*256;
            int r = idx >> 4, c = idx & 15;
            uint32_t so = sw256(r*256 + c*16);
            cp16(Kd + so, Kg + (size_t)r*QKVN + c*8);
            cp16(Vd + so, Vg + (size_t)r*QKVN + c*8);
        }
        cp_commit();
    };
    issueKV(0, 0);
    cp_wait0();
    __syncthreads();

    uint32_t qf[8][4];
    #pragma unroll
    for (int ks = 0; ks < 8; ks++){
        int row = wid*16 + (lane&7) + ((lane>>3)&1)*8;
        int ch  = 2*ks + (lane>>4);
        ldm4(qf[ks], sb + FQ_OFF + sw256(row*256 + ch*16));
    }

    float m0 = -1e30f, m1 = -1e30f, l0 = 0.f, l1 = 0.f;
    float oacc[16][4];
    #pragma unroll
    for (int i=0;i<16;i++)
        #pragma unroll
        for (int j=0;j<4;j++) oacc[i][j] = 0.f;

    const int nkt = SEQ / 64;     // 32
    for (int kt = 0; kt < nkt; kt++){
        if (kt > 0){ cp_wait0(); __syncthreads(); }
        if (kt+1 < nkt) issueKV(kt+1, (kt+1)&1);
        const uint32_t sK = sb + FK_OFF + (kt&1)*16*1024;
        const uint32_t sV = sb + FV_OFF + (kt&1)*16*1024;

        float sacc[8][4];
        #pragma unroll
        for (int i=0;i<8;i++)
            #pragma unroll
            for (int j=0;j<4;j++) sacc[i][j] = 0.f;
        #pragma unroll
        for (int ks = 0; ks < 8; ks++){
            #pragma unroll
            for (int ntp = 0; ntp < 4; ntp++){
                uint32_t kf[4];
                int row = ntp*16 + ((lane>>4)&1)*8 + (lane&7);
                int ch  = 2*ks + ((lane>>3)&1);
                ldm4(kf, sK + sw256(row*256 + ch*16));
                mma_f16(sacc[2*ntp],   qf[ks], kf[0], kf[1]);
                mma_f16(sacc[2*ntp+1], qf[ks], kf[2], kf[3]);
            }
        }

        float mx0 = -1e30f, mx1 = -1e30f;
        #pragma unroll
        for (int nt=0; nt<8; nt++){
            mx0 = fmaxf(mx0, fmaxf(sacc[nt][0], sacc[nt][1]));
            mx1 = fmaxf(mx1, fmaxf(sacc[nt][2], sacc[nt][3]));
        }
        mx0 = fmaxf(mx0, __shfl_xor_sync(~0u, mx0, 1));
        mx0 = fmaxf(mx0, __shfl_xor_sync(~0u, mx0, 2));
        mx1 = fmaxf(mx1, __shfl_xor_sync(~0u, mx1, 1));
        mx1 = fmaxf(mx1, __shfl_xor_sync(~0u, mx1, 2));
        float mn0 = fmaxf(m0, mx0), mn1 = fmaxf(m1, mx1);
        float cr0 = __expf(m0 - mn0), cr1 = __expf(m1 - mn1);
        m0 = mn0; m1 = mn1;
        float rs0 = 0.f, rs1 = 0.f;
        #pragma unroll
        for (int nt=0; nt<8; nt++){
            sacc[nt][0] = __expf(sacc[nt][0] - mn0);
            sacc[nt][1] = __expf(sacc[nt][1] - mn0);
            sacc[nt][2] = __expf(sacc[nt][2] - mn1);
            sacc[nt][3] = __expf(sacc[nt][3] - mn1);
            rs0 += sacc[nt][0] + sacc[nt][1];
            rs1 += sacc[nt][2] + sacc[nt][3];
        }
        rs0 += __shfl_xor_sync(~0u, rs0, 1); rs0 += __shfl_xor_sync(~0u, rs0, 2);
        rs1 += __shfl_xor_sync(~0u, rs1, 1); rs1 += __shfl_xor_sync(~0u, rs1, 2);
        l0 = l0*cr0 + rs0; l1 = l1*cr1 + rs1;
        #pragma unroll
        for (int i=0;i<16;i++){
            oacc[i][0] *= cr0; oacc[i][1] *= cr0;
            oacc[i][2] *= cr1; oacc[i][3] *= cr1;
        }

        #pragma unroll
        for (int kv = 0; kv < 4; kv++){
            uint32_t pf[4];
            pf[0] = pkh2(sacc[2*kv][0],   sacc[2*kv][1]);
            pf[1] = pkh2(sacc[2*kv][2],   sacc[2*kv][3]);
            pf[2] = pkh2(sacc[2*kv+1][0], sacc[2*kv+1][1]);
            pf[3] = pkh2(sacc[2*kv+1][2], sacc[2*kv+1][3]);
            #pragma unroll
            for (int ntp = 0; ntp < 8; ntp++){
                uint32_t vf[4];
                int row = kv*16 + (lane&7) + ((lane>>3)&1)*8;
                int ch  = 2*ntp + (lane>>4);
                ldm4t(vf, sV + sw256(row*256 + ch*16));
                mma_f16(oacc[2*ntp],   pf, vf[0], vf[1]);
                mma_f16(oacc[2*ntp+1], pf, vf[2], vf[3]);
            }
        }
    }

    float inv0 = 1.f/l0, inv1 = 1.f/l1;
    int r = wid*16 + (lane>>2);
    __half* Og0 = O + ((size_t)(q0 + r))*DM + h*HDIM;
    __half* Og1 = O + ((size_t)(q0 + r + 8))*DM + h*HDIM;
    #pragma unroll
    for (int nt=0; nt<16; nt++){
        int c = nt*8 + (lane&3)*2;
        *(uint32_t*)(Og0 + c) = pkh2(oacc[nt][0]*inv0, oacc[nt][1]*inv0);
        *(uint32_t*)(Og1 + c) = pkh2(oacc[nt][2]*inv1, oacc[nt][3]*inv1);
    }
}

// ---------------- launch: 3-stream pipeline (split weight-ready events) -----
extern "C" void kernel_launch(void* const* d_in, const int* in_sizes, int n_in,
                              void* d_out, int out_size){
    const float* x   = (const float*)d_in[0];
    const float* fc  = (const float*)d_in[1];
    const float* fs  = (const float*)d_in[2];
    const float* wq  = (const float*)d_in[3];
    const float* wk  = (const float*)d_in[4];
    const float* wv  = (const float*)d_in[5];
    const float* wo  = (const float*)d_in[6];
    const float* w1  = (const float*)d_in[7];
    const float* w2  = (const float*)d_in[8];
    const float* w3  = (const float*)d_in[9];
    const float* anw = (const float*)d_in[10];
    const float* fnw = (const float*)d_in[11];
    float* out = (float*)d_out;

    __half *xn,*qkv,*attn,*hn,*ffa,*wqkvH,*woH,*w13H,*w2H;
    float  *h;
    cudaGetSymbolAddress((void**)&xn,    g_xn);
    cudaGetSymbolAddress((void**)&qkv,   g_qkv);
    cudaGetSymbolAddress((void**)&attn,  g_attn);
    cudaGetSymbolAddress((void**)&h,     g_h);
    cudaGetSymbolAddress((void**)&hn,    g_hn);
    cudaGetSymbolAddress((void**)&ffa,   g_ffa);
    cudaGetSymbolAddress((void**)&wqkvH, g_wqkv);
    cudaGetSymbolAddress((void**)&woH,   g_wo);
    cudaGetSymbolAddress((void**)&w13H,  g_w13);
    cudaGetSymbolAddress((void**)&w2H,   g_w2);

    cudaFuncSetAttribute((const void*)gemm_kernel<false,true,true,false>,  cudaFuncAttributeMaxDynamicSharedMemorySize, GEMM_SMEM);
    cudaFuncSetAttribute((const void*)gemm_kernel<true,false,false,false>, cudaFuncAttributeMaxDynamicSharedMemorySize, GEMM_SMEM);
    cudaFuncSetAttribute((const void*)gemm_kernel<false,true,false,true>,  cudaFuncAttributeMaxDynamicSharedMemorySize, GEMM_SMEM);
    cudaFuncSetAttribute((const void*)flash_kernel, cudaFuncAttributeMaxDynamicSharedMemorySize, FLASH_SMEM);

    const int thr = 256;
    const int t16 = DM*DM/16;     // 262144 (qkv 16-elem chunks)
    const int t8p = DM*HID/8;     // 1441792
    dim3 gq(QKVN/128, HTOK/128);  // (48,16)
    dim3 gd(DM/128,  HTOK/128);   // (16,16)
    dim3 gffh(FFN2/128, HTOK/128);// (88,16)
    dim3 gfl(SEQ/128, NH, 1);     // (16,16,1)

    // fork all three pipelines off the capture stream
    cudaEventRecord(g_e0, 0);
    cudaStreamWaitEvent(g_s1, g_e0, 0);
    cudaStreamWaitEvent(g_s2, g_e0, 0);
    cudaStreamWaitEvent(g_s3, g_e0, 0);

    // s3: weight converts in dependency order: qkv -> ow2 -> w13.
    cvt_qkv<<<dim3((t16+thr-1)/thr, 3), thr, 0, g_s3>>>(wq, wk, wv, wqkvH);
    cudaEventRecord(g_eQ, g_s3);
    cvt_ow2<<<dim3((t8p+thr-1)/thr, 2), thr, 0, g_s3>>>(wo, w2, woH, w2H);
    cudaEventRecord(g_eW, g_s3);
    cvt_w13<<<(t8p+thr-1)/thr, thr, 0, g_s3>>>(w1, w3, w13H);
    cudaEventRecord(g_eF, g_s3);

    // ---- stream 1: batch 0 (rows 0..2047) ----
    {
        const size_t r0 = 0;
        rmsnorm_kernel<<<HTOK, 256, 0, g_s1>>>(x + r0*DM, anw, xn + r0*DM);
        cudaStreamWaitEvent(g_s1, g_eQ, 0);
        gemm_kernel<false,true,true,false><<<gq, 128, GEMM_SMEM, g_s1>>>(
            xn + r0*DM, wqkvH, nullptr, qkv + r0*QKVN, HTOK, QKVN, DM, fc, fs);
        flash_kernel<<<gfl, 256, FLASH_SMEM, g_s1>>>(qkv + r0*QKVN, attn + r0*DM);
        cudaStreamWaitEvent(g_s1, g_eW, 0);
        gemm_kernel<true,false,false,false><<<gd, 128, GEMM_SMEM, g_s1>>>(
            attn + r0*DM, woH, x + r0*DM, h + r0*DM, HTOK, DM, DM, nullptr, nullptr);
        rmsnorm_kernel<<<HTOK, 256, 0, g_s1>>>(h + r0*DM, fnw, hn + r0*DM);
        cudaStreamWaitEvent(g_s1, g_eF, 0);
        gemm_kernel<false,true,false,true><<<gffh, 128, GEMM_SMEM, g_s1>>>(
            hn + r0*DM, w13H, nullptr, ffa + r0*HID, HTOK, FFN2, DM, nullptr, nullptr);
        gemm_kernel<true,false,false,false><<<gd, 128, GEMM_SMEM, g_s1>>>(
            ffa + r0*HID, w2H, h + r0*DM, out + r0*DM, HTOK, DM, HID, nullptr, nullptr);
        cudaEventRecord(g_e1, g_s1);
    }

    // ---- stream 2: batch 1 (rows 2048..4095) ----
    {
        const size_t r0 = HTOK;
        rmsnorm_kernel<<<HTOK, 256, 0, g_s2>>>(x + r0*DM, anw, xn + r0*DM);
        cudaStreamWaitEvent(g_s2, g_eQ, 0);
        gemm_kernel<false,true,true,false><<<gq, 128, GEMM_SMEM, g_s2>>>(
            xn + r0*DM, wqkvH, nullptr, qkv + r0*QKVN, HTOK, QKVN, DM, fc, fs);
        flash_kernel<<<gfl, 256, FLASH_SMEM, g_s2>>>(qkv + r0*QKVN, attn + r0*DM);
        cudaStreamWaitEvent(g_s2, g_eW, 0);
        gemm_kernel<true,false,false,false><<<gd, 128, GEMM_SMEM, g_s2>>>(
            attn + r0*DM, woH, x + r0*DM, h + r0*DM, HTOK, DM, DM, nullptr, nullptr);
        rmsnorm_kernel<<<HTOK, 256, 0, g_s2>>>(h + r0*DM, fnw, hn + r0*DM);
        cudaStreamWaitEvent(g_s2, g_eF, 0);
        gemm_kernel<false,true,false,true><<<gffh, 128, GEMM_SMEM, g_s2>>>(
            hn + r0*DM, w13H, nullptr, ffa + r0*HID, HTOK, FFN2, DM, nullptr, nullptr);
        gemm_kernel<true,false,false,false><<<gd, 128, GEMM_SMEM, g_s2>>>(
            ffa + r0*HID, w2H, h + r0*DM, out + r0*DM, HTOK, DM, HID, nullptr, nullptr);
        cudaEventRecord(g_e2, g_s2);
    }

    // join back to the capture stream
    cudaStreamWaitEvent(0, g_e1, 0);
    cudaStreamWaitEvent(0, g_e2, 0);
}

// round 17
// speedup vs baseline: 1.0224x; 1.0024x over previous
#include <cuda_runtime.h>
#include <cuda_fp16.h>
#include <math.h>
#include <stdint.h>

#define BSZ   2
#define SEQ   2048
#define DM    2048
#define NH    16
#define HDIM  128
#define HID   5632
#define NTOK  (BSZ*SEQ)     // 4096
#define HTOK  (NTOK/2)      // 2048 rows per batch half
#define QKVN  (3*DM)        // 6144
#define FFN2  (2*HID)       // 11264

// ---------------- scratch (no allocation allowed -> __device__ globals) ----
__device__ __half g_xn  [NTOK*(size_t)DM];
__device__ __half g_qkv [NTOK*(size_t)QKVN];
__device__ __half g_attn[NTOK*(size_t)DM];
__device__ float  g_h   [NTOK*(size_t)DM];
__device__ __half g_hn  [NTOK*(size_t)DM];
__device__ __half g_ffa [NTOK*(size_t)HID];
// fp16 weights, [K,N] layout (wq|wk|wv fused; w1/w3 interleaved by 8 cols)
__device__ __half g_wqkv[DM*(size_t)QKVN];
__device__ __half g_wo  [DM*(size_t)DM];
__device__ __half g_w13 [DM*(size_t)FFN2];
__device__ __half g_w2  [HID*(size_t)DM];

// ---------------- streams/events created at static init (pre-checkpoint) ---
static cudaStream_t g_s1, g_s2, g_s3;
static cudaEvent_t  g_e0, g_eQ1, g_eQ2, g_eQ3, g_eW, g_eF, g_e1, g_e2;
static struct StreamInit {
    StreamInit(){
        cudaStreamCreateWithFlags(&g_s1, cudaStreamNonBlocking);
        cudaStreamCreateWithFlags(&g_s2, cudaStreamNonBlocking);
        cudaStreamCreateWithFlags(&g_s3, cudaStreamNonBlocking);
        cudaEventCreateWithFlags(&g_e0,  cudaEventDisableTiming);
        cudaEventCreateWithFlags(&g_eQ1, cudaEventDisableTiming);
        cudaEventCreateWithFlags(&g_eQ2, cudaEventDisableTiming);
        cudaEventCreateWithFlags(&g_eQ3, cudaEventDisableTiming);
        cudaEventCreateWithFlags(&g_eW,  cudaEventDisableTiming);
        cudaEventCreateWithFlags(&g_eF,  cudaEventDisableTiming);
        cudaEventCreateWithFlags(&g_e1,  cudaEventDisableTiming);
        cudaEventCreateWithFlags(&g_e2,  cudaEventDisableTiming);
    }
} g_stream_init;

// ---------------- helpers --------------------------------------------------
__device__ __forceinline__ uint32_t smem_u32(const void* p){
    uint32_t a;
    asm("{ .reg .u64 t; cvta.to.shared.u64 t, %1; cvt.u32.u64 %0, t; }" : "=r"(a) : "l"(p));
    return a;
}
__device__ __forceinline__ void cp16(void* dst, const void* src){
    unsigned d = (unsigned)__cvta_generic_to_shared(dst);
    asm volatile("cp.async.cg.shared.global [%0], [%1], 16;" :: "r"(d), "l"(src));
}
__device__ __forceinline__ void cp_commit(){ asm volatile("cp.async.commit_group;"); }
__device__ __forceinline__ void cp_wait0(){ asm volatile("cp.async.wait_group 0;"); }
__device__ __forceinline__ void cp_wait1(){ asm volatile("cp.async.wait_group 1;"); }

__device__ __forceinline__ void ldm4(uint32_t r[4], uint32_t addr){
    asm volatile("ldmatrix.sync.aligned.m8n8.x4.shared.b16 {%0,%1,%2,%3}, [%4];"
        : "=r"(r[0]), "=r"(r[1]), "=r"(r[2]), "=r"(r[3]) : "r"(addr));
}
__device__ __forceinline__ void ldm4t(uint32_t r[4], uint32_t addr){
    asm volatile("ldmatrix.sync.aligned.m8n8.x4.trans.shared.b16 {%0,%1,%2,%3}, [%4];"
        : "=r"(r[0]), "=r"(r[1]), "=r"(r[2]), "=r"(r[3]) : "r"(addr));
}
__device__ __forceinline__ void mma_f16(float c[4], const uint32_t a[4], uint32_t b0, uint32_t b1){
    asm volatile("mma.sync.aligned.m16n8k16.row.col.f32.f16.f16.f32 "
        "{%0,%1,%2,%3},{%4,%5,%6,%7},{%8,%9},{%0,%1,%2,%3};"
        : "+f"(c[0]), "+f"(c[1]), "+f"(c[2]), "+f"(c[3])
        : "r"(a[0]), "r"(a[1]), "r"(a[2]), "r"(a[3]), "r"(b0), "r"(b1));
}
__device__ __forceinline__ uint32_t pkh2(float a, float b){
    __half2 h = __floats2half2_rn(a, b);
    return reinterpret_cast<uint32_t&>(h);
}
__device__ __forceinline__ float siluf(float x){ return x / (1.f + __expf(-x)); }
// swizzles (relative byte offsets; conflict-free ldmatrix phases)
__device__ __forceinline__ uint32_t swA(uint32_t o){ return o ^ (((o >> 7) & 7) << 4); }   // 128B rows
__device__ __forceinline__ uint32_t sw256(uint32_t o){ return o ^ (((o >> 8) & 7) << 4); } // 256B rows

// ------- weight convert prepass: fp32[K,Ns] -> fp16 ------------------------
__device__ __forceinline__ void cvt8_body(const float* __restrict__ src, __half* __restrict__ dst,
                                          int Ns, int Nd, int col0, int total8){
    int idx = blockIdx.x*blockDim.x + threadIdx.x;
    if (idx >= total8) return;
    int ns8 = Ns >> 3;
    int k = idx / ns8, j = (idx - k*ns8) << 3;
    const float4* s = (const float4*)(src + (size_t)k*Ns + j);
    float4 v0 = s[0], v1 = s[1];
    uint4 o;
    o.x = pkh2(v0.x, v0.y); o.y = pkh2(v0.z, v0.w);
    o.z = pkh2(v1.x, v1.y); o.w = pkh2(v1.z, v1.w);
    *(uint4*)(dst + (size_t)k*Nd + j + col0) = o;
}

// one DMxDM source -> columns [col0, col0+DM) of the fused qkv weight
__global__ void cvt_one(const float* __restrict__ src, __half* __restrict__ dst, int col0){
    int idx = blockIdx.x*blockDim.x + threadIdx.x;
    if (idx >= DM*DM/16) return;
    int ns16 = DM >> 4;
    int k = idx / ns16, j = (idx - k*ns16) << 4;
    const float4* s = (const float4*)(src + (size_t)k*DM + j);
    float4 v0 = s[0], v1 = s[1], v2 = s[2], v3 = s[3];
    uint4 o0, o1;
    o0.x = pkh2(v0.x,v0.y); o0.y = pkh2(v0.z,v0.w);
    o0.z = pkh2(v1.x,v1.y); o0.w = pkh2(v1.z,v1.w);
    o1.x = pkh2(v2.x,v2.y); o1.y = pkh2(v2.z,v2.w);
    o1.z = pkh2(v3.x,v3.y); o1.w = pkh2(v3.z,v3.w);
    __half* d = dst + (size_t)k*QKVN + col0 + j;
    *(uint4*)(d)     = o0;
    *(uint4*)(d + 8) = o1;
}
// w1/w3 interleaved by 8 cols; contiguous 32B stores
__global__ void cvt_w13(const float* __restrict__ w1, const float* __restrict__ w3,
                        __half* __restrict__ dst){
    int idx = blockIdx.x*blockDim.x + threadIdx.x;
    const int total8 = DM*HID/8;
    if (idx >= total8) return;
    int ns8 = HID >> 3;
    int k = idx / ns8, j8 = idx - k*ns8;
    const float4* a = (const float4*)(w1 + (size_t)k*HID + j8*8);
    const float4* b = (const float4*)(w3 + (size_t)k*HID + j8*8);
    float4 a0 = a[0], a1 = a[1];
    float4 b0 = b[0], b1 = b[1];
    uint4 o1 = make_uint4(pkh2(a0.x,a0.y), pkh2(a0.z,a0.w), pkh2(a1.x,a1.y), pkh2(a1.z,a1.w));
    uint4 o3 = make_uint4(pkh2(b0.x,b0.y), pkh2(b0.z,b0.w), pkh2(b1.x,b1.y), pkh2(b1.z,b1.w));
    __half* d = dst + (size_t)k*FFN2 + j8*16;
    *(uint4*)(d)     = o1;
    *(uint4*)(d + 8) = o3;
}
__global__ void cvt_ow2(const float* wo, const float* w2, __half* dwo, __half* dw2){
    if (blockIdx.y == 0) cvt8_body(wo, dwo, DM, DM, 0, DM*DM/8);
    else                 cvt8_body(w2, dw2, DM, DM, 0, HID*DM/8);
}

// ---------------- rmsnorm (fp32 in -> fp16 out, vectorized) ----------------
__global__ void rmsnorm_kernel(const float* __restrict__ x, const float* __restrict__ w,
                               __half* __restrict__ out){
    int row = blockIdx.x;
    const float4* xr = (const float4*)(x + (size_t)row*DM);
    float4 v0 = xr[threadIdx.x], v1 = xr[threadIdx.x + 256];
    float ss = v0.x*v0.x + v0.y*v0.y + v0.z*v0.z + v0.w*v0.w
             + v1.x*v1.x + v1.y*v1.y + v1.z*v1.z + v1.w*v1.w;
    __shared__ float red[8];
    #pragma unroll
    for (int o = 16; o; o >>= 1) ss += __shfl_xor_sync(~0u, ss, o);
    if ((threadIdx.x & 31) == 0) red[threadIdx.x >> 5] = ss;
    __syncthreads();
    if (threadIdx.x == 0){
        float t = 0.f;
        #pragma unroll
        for (int i = 0; i < 8; i++) t += red[i];
        red[0] = t;
    }
    __syncthreads();
    float inv = rsqrtf(red[0] / (float)DM + 1e-5f);
    const float4* w4 = (const float4*)w;
    uint2* o2 = (uint2*)(out + (size_t)row*DM);
    float4 a = w4[threadIdx.x], b = w4[threadIdx.x + 256];
    o2[threadIdx.x]       = make_uint2(pkh2(v0.x*inv*a.x, v0.y*inv*a.y), pkh2(v0.z*inv*a.z, v0.w*inv*a.w));
    o2[threadIdx.x + 256] = make_uint2(pkh2(v1.x*inv*b.x, v1.y*inv*b.y), pkh2(v1.z*inv*b.z, v1.w*inv*b.w));
}

// ================= fp16 GEMM: C[M,N] = A[M,K] @ B[K,N] =====================
// 128x128 block, 4 warps of 64x64, BK=64, 3-stage cp.async, 2 CTAs/SM.
#define GSTG_BYTES (32*1024)
#define GEMM_SMEM  (3*GSTG_BYTES)     // 98304 -> 2 CTAs/SM
#define QSCALE 0.08838834764831845f   // 1/sqrt(128), folded into Q

template<bool ADD, bool HOUT, bool ROPE, bool SILU>
__global__ void __launch_bounds__(128, 2)
gemm_kernel(const __half* __restrict__ A, const __half* __restrict__ B,
            const float* __restrict__ Add, void* __restrict__ Cv,
            int M, int N, int K,
            const float* __restrict__ fc, const float* __restrict__ fs)
{
    extern __shared__ char smem[];
    const uint32_t sb = smem_u32(smem);
    const int tid = threadIdx.x, lane = tid & 31, wid = tid >> 5;   // 4 warps
    const int wm = (wid >> 1) * 64;
    const int wn = (wid & 1) * 64;
    const int bm = blockIdx.y * 128, bn = blockIdx.x * 128;

    float acc[4][8][4];
    #pragma unroll
    for (int i=0;i<4;i++)
        #pragma unroll
        for (int j=0;j<8;j++)
            #pragma unroll
            for (int r=0;r<4;r++) acc[i][j][r] = 0.f;

    const int nk = K / 64;

    auto issue = [&](int kt, int st){
        char* Ad = smem + st*GSTG_BYTES;
        const __half* Ag = A + (size_t)bm*K + kt*64;
        #pragma unroll
        for (int i = 0; i < 8; i++){
            int idx = tid + i*128;            // 0..1023
            int m = idx >> 3, c = idx & 7;
            cp16(Ad + swA(m*128 + c*16), Ag + (size_t)m*K + c*8);
        }
        char* Bd = Ad + 16*1024;
        const __half* Bg = B + (size_t)(kt*64)*N + bn;
        #pragma unroll
        for (int i = 0; i < 8; i++){
            int idx = tid + i*128;            // 0..1023
            int k = idx >> 4, c = idx & 15;
            cp16(Bd + sw256(k*256 + c*16), Bg + (size_t)k*N + c*8);
        }
        cp_commit();
    };

    issue(0, 0); issue(1, 1);
    int cur = 0, nxt = 2;
    for (int kt = 0; kt < nk; kt++){
        cp_wait1();
        __syncthreads();
        if (kt+2 < nk) issue(kt+2, nxt);
        const uint32_t sA = sb + cur*GSTG_BYTES;
        const uint32_t sB = sA + 16*1024;
        if (++cur == 3) cur = 0;
        if (++nxt == 3) nxt = 0;
        #pragma unroll
        for (int ks = 0; ks < 4; ks++){
            uint32_t af[4][4];
            #pragma unroll
            for (int mt = 0; mt < 4; mt++){
                int row = wm + mt*16 + (lane&7) + ((lane>>3)&1)*8;
                int ch  = 2*ks + (lane>>4);
                ldm4(af[mt], sA + swA(row*128 + ch*16));
            }
            uint32_t bf[4][4];
            #pragma unroll
            for (int ntp = 0; ntp < 4; ntp++){
                int krow = ks*16 + (lane&7) + ((lane>>3)&1)*8;
                int ch   = ((wn + ntp*16) >> 3) + (lane>>4);
                ldm4t(bf[ntp], sB + sw256(krow*256 + ch*16));
            }
            #pragma unroll
            for (int mt = 0; mt < 4; mt++)
                #pragma unroll
                for (int ntp = 0; ntp < 4; ntp++){
                    mma_f16(acc[mt][2*ntp],   af[mt], bf[ntp][0], bf[ntp][1]);
                    mma_f16(acc[mt][2*ntp+1], af[mt], bf[ntp][2], bf[ntp][3]);
                }
        }
    }

    // ---------------- epilogue ----------------
    if (SILU){
        __half* C = (__half*)Cv;
        const int NO = N >> 1;    // HID
        #pragma unroll
        for (int mt = 0; mt < 4; mt++){
            int r0 = bm + wm + mt*16 + (lane>>2);
            #pragma unroll
            for (int ntp = 0; ntp < 4; ntp++){
                int j = ((bn + wn) >> 1) + ntp*8 + (lane&3)*2;
                const float* a1 = acc[mt][2*ntp];
                const float* a3 = acc[mt][2*ntp+1];
                *(uint32_t*)(C + (size_t)r0*NO + j) =
                    pkh2(siluf(a1[0])*a3[0], siluf(a1[1])*a3[1]);
                *(uint32_t*)(C + (size_t)(r0+8)*NO + j) =
                    pkh2(siluf(a1[2])*a3[2], siluf(a1[3])*a3[3]);
            }
        }
        return;
    }
    #pragma unroll
    for (int mt = 0; mt < 4; mt++){
        #pragma unroll
        for (int nt = 0; nt < 8; nt++){
            int r = bm + wm + mt*16 + (lane>>2);
            int c = bn + wn + nt*8 + (lane&3)*2;
            float2 v0 = make_float2(acc[mt][nt][0], acc[mt][nt][1]);
            float2 v1 = make_float2(acc[mt][nt][2], acc[mt][nt][3]);
            if (ADD){
                const float* A0 = Add + (size_t)r*N + c;
                const float* A1 = Add + (size_t)(r+8)*N + c;
                v0.x += A0[0]; v0.y += A0[1];
                v1.x += A1[0]; v1.y += A1[1];
            }
            if (ROPE && c < 2*DM){
                int i = (c & (HDIM-1)) >> 1;
                int s0 = r & (SEQ-1), s1 = (r+8) & (SEQ-1);
                float c0 = fc[s0*64 + i], sn0 = fs[s0*64 + i];
                float c1 = fc[s1*64 + i], sn1 = fs[s1*64 + i];
                float a = v0.x, b = v0.y;
                v0.x = a*c0 - b*sn0; v0.y = a*sn0 + b*c0;
                a = v1.x; b = v1.y;
                v1.x = a*c1 - b*sn1; v1.y = a*sn1 + b*c1;
                if (c < DM){   // q slice: fold softmax scale
                    v0.x *= QSCALE; v0.y *= QSCALE;
                    v1.x *= QSCALE; v1.y *= QSCALE;
                }
            }
            if (HOUT){
                __half* C = (__half*)Cv;
                *(uint32_t*)(C + (size_t)r*N + c)     = pkh2(v0.x, v0.y);
                *(uint32_t*)(C + (size_t)(r+8)*N + c) = pkh2(v1.x, v1.y);
            } else {
                float* C = (float*)Cv;
                *(float2*)(C + (size_t)r*N + c)     = v0;
                *(float2*)(C + (size_t)(r+8)*N + c) = v1;
            }
        }
    }
}

// ---------------- flash attention, BQ=128, 256 threads, P in registers -----
// Two-stage KV double buffer, unconditional online-softmax rescale.
#define FQ_OFF  0
#define FK_OFF  (32*1024)
#define FV_OFF  (64*1024)
#define FLASH_SMEM (96*1024)

__global__ void __launch_bounds__(256)
flash_kernel(const __half* __restrict__ QKV, __half* __restrict__ O)
{
    extern __shared__ char smem[];
    const uint32_t sb = smem_u32(smem);
    const int tid = threadIdx.x, lane = tid & 31, wid = tid >> 5;
    const int qt = blockIdx.x, h = blockIdx.y;
    const int q0 = qt*128;

    {   // Q: 128 rows x 256B (pre-scaled by 1/sqrt(HD) in QKV epilogue)
        const __half* Qg = QKV + (size_t)q0*QKVN + h*HDIM;
        #pragma unroll
        for (int i = 0; i < 8; i++){
            int idx = tid + i*256;
            int r = idx >> 4, c = idx & 15;
            cp16(smem + FQ_OFF + sw256(r*256 + c*16), Qg + (size_t)r*QKVN + c*8);
        }
    }
    auto issueKV = [&](int kt, int st){
        const __half* Kg = QKV + (size_t)(kt*64)*QKVN + DM   + h*HDIM;
        const __half* Vg = QKV + (size_t)(kt*64)*QKVN + 2*DM + h*HDIM;
        char* Kd = smem + FK_OFF + st*16*1024;
        char* Vd = smem + FV_OFF + st*16*1024;
        #pragma unroll
        for (int i = 0; i < 4; i++){
            int idx = tid + i*256;
            int r = idx >> 4, c = idx & 15;
            uint32_t so = sw256(r*256 + c*16);
            cp16(Kd + so, Kg + (size_t)r*QKVN + c*8);
            cp16(Vd + so, Vg + (size_t)r*QKVN + c*8);
        }
        cp_commit();
    };
    issueKV(0, 0);
    cp_wait0();
    __syncthreads();

    uint32_t qf[8][4];
    #pragma unroll
    for (int ks = 0; ks < 8; ks++){
        int row = wid*16 + (lane&7) + ((lane>>3)&1)*8;
        int ch  = 2*ks + (lane>>4);
        ldm4(qf[ks], sb + FQ_OFF + sw256(row*256 + ch*16));
    }

    float m0 = -1e30f, m1 = -1e30f, l0 = 0.f, l1 = 0.f;
    float oacc[16][4];
    #pragma unroll
    for (int i=0;i<16;i++)
        #pragma unroll
        for (int j=0;j<4;j++) oacc[i][j] = 0.f;

    const int nkt = SEQ / 64;     // 32
    for (int kt = 0; kt < nkt; kt++){
        if (kt > 0){ cp_wait0(); __syncthreads(); }
        if (kt+1 < nkt) issueKV(kt+1, (kt+1)&1);
        const uint32_t sK = sb + FK_OFF + (kt&1)*16*1024;
        const uint32_t sV = sb + FV_OFF + (kt&1)*16*1024;

        float sacc[8][4];
        #pragma unroll
        for (int i=0;i<8;i++)
            #pragma unroll
            for (int j=0;j<4;j++) sacc[i][j] = 0.f;
        #pragma unroll
        for (int ks = 0; ks < 8; ks++){
            #pragma unroll
            for (int ntp = 0; ntp < 4; ntp++){
                uint32_t kf[4];
                int row = ntp*16 + ((lane>>4)&1)*8 + (lane&7);
                int ch  = 2*ks + ((lane>>3)&1);
                ldm4(kf, sK + sw256(row*256 + ch*16));
                mma_f16(sacc[2*ntp],   qf[ks], kf[0], kf[1]);
                mma_f16(sacc[2*ntp+1], qf[ks], kf[2], kf[3]);
            }
        }

        float mx0 = -1e30f, mx1 = -1e30f;
        #pragma unroll
        for (int nt=0; nt<8; nt++){
            mx0 = fmaxf(mx0, fmaxf(sacc[nt][0], sacc[nt][1]));
            mx1 = fmaxf(mx1, fmaxf(sacc[nt][2], sacc[nt][3]));
        }
        mx0 = fmaxf(mx0, __shfl_xor_sync(~0u, mx0, 1));
        mx0 = fmaxf(mx0, __shfl_xor_sync(~0u, mx0, 2));
        mx1 = fmaxf(mx1, __shfl_xor_sync(~0u, mx1, 1));
        mx1 = fmaxf(mx1, __shfl_xor_sync(~0u, mx1, 2));
        float mn0 = fmaxf(m0, mx0), mn1 = fmaxf(m1, mx1);
        float cr0 = __expf(m0 - mn0), cr1 = __expf(m1 - mn1);
        m0 = mn0; m1 = mn1;
        float rs0 = 0.f, rs1 = 0.f;
        #pragma unroll
        for (int nt=0; nt<8; nt++){
            sacc[nt][0] = __expf(sacc[nt][0] - mn0);
            sacc[nt][1] = __expf(sacc[nt][1] - mn0);
            sacc[nt][2] = __expf(sacc[nt][2] - mn1);
            sacc[nt][3] = __expf(sacc[nt][3] - mn1);
            rs0 += sacc[nt][0] + sacc[nt][1];
            rs1 += sacc[nt][2] + sacc[nt][3];
        }
        rs0 += __shfl_xor_sync(~0u, rs0, 1); rs0 += __shfl_xor_sync(~0u, rs0, 2);
        rs1 += __shfl_xor_sync(~0u, rs1, 1); rs1 += __shfl_xor_sync(~0u, rs1, 2);
        l0 = l0*cr0 + rs0; l1 = l1*cr1 + rs1;
        #pragma unroll
        for (int i=0;i<16;i++){
            oacc[i][0] *= cr0; oacc[i][1] *= cr0;
            oacc[i][2] *= cr1; oacc[i][3] *= cr1;
        }

        #pragma unroll
        for (int kv = 0; kv < 4; kv++){
            uint32_t pf[4];
            pf[0] = pkh2(sacc[2*kv][0],   sacc[2*kv][1]);
            pf[1] = pkh2(sacc[2*kv][2],   sacc[2*kv][3]);
            pf[2] = pkh2(sacc[2*kv+1][0], sacc[2*kv+1][1]);
            pf[3] = pkh2(sacc[2*kv+1][2], sacc[2*kv+1][3]);
            #pragma unroll
            for (int ntp = 0; ntp < 8; ntp++){
                uint32_t vf[4];
                int row = kv*16 + (lane&7) + ((lane>>3)&1)*8;
                int ch  = 2*ntp + (lane>>4);
                ldm4t(vf, sV + sw256(row*256 + ch*16));
                mma_f16(oacc[2*ntp],   pf, vf[0], vf[1]);
                mma_f16(oacc[2*ntp+1], pf, vf[2], vf[3]);
            }
        }
    }

    float inv0 = 1.f/l0, inv1 = 1.f/l1;
    int r = wid*16 + (lane>>2);
    __half* Og0 = O + ((size_t)(q0 + r))*DM + h*HDIM;
    __half* Og1 = O + ((size_t)(q0 + r + 8))*DM + h*HDIM;
    #pragma unroll
    for (int nt=0; nt<16; nt++){
        int c = nt*8 + (lane&3)*2;
        *(uint32_t*)(Og0 + c) = pkh2(oacc[nt][0]*inv0, oacc[nt][1]*inv0);
        *(uint32_t*)(Og1 + c) = pkh2(oacc[nt][2]*inv1, oacc[nt][3]*inv1);
    }
}

// ---------------- launch: 3-stream pipeline, parallel qkv weight convert ----
extern "C" void kernel_launch(void* const* d_in, const int* in_sizes, int n_in,
                              void* d_out, int out_size){
    const float* x   = (const float*)d_in[0];
    const float* fc  = (const float*)d_in[1];
    const float* fs  = (const float*)d_in[2];
    const float* wq  = (const float*)d_in[3];
    const float* wk  = (const float*)d_in[4];
    const float* wv  = (const float*)d_in[5];
    const float* wo  = (const float*)d_in[6];
    const float* w1  = (const float*)d_in[7];
    const float* w2  = (const float*)d_in[8];
    const float* w3  = (const float*)d_in[9];
    const float* anw = (const float*)d_in[10];
    const float* fnw = (const float*)d_in[11];
    float* out = (float*)d_out;

    __half *xn,*qkv,*attn,*hn,*ffa,*wqkvH,*woH,*w13H,*w2H;
    float  *h;
    cudaGetSymbolAddress((void**)&xn,    g_xn);
    cudaGetSymbolAddress((void**)&qkv,   g_qkv);
    cudaGetSymbolAddress((void**)&attn,  g_attn);
    cudaGetSymbolAddress((void**)&h,     g_h);
    cudaGetSymbolAddress((void**)&hn,    g_hn);
    cudaGetSymbolAddress((void**)&ffa,   g_ffa);
    cudaGetSymbolAddress((void**)&wqkvH, g_wqkv);
    cudaGetSymbolAddress((void**)&woH,   g_wo);
    cudaGetSymbolAddress((void**)&w13H,  g_w13);
    cudaGetSymbolAddress((void**)&w2H,   g_w2);

    cudaFuncSetAttribute((const void*)gemm_kernel<false,true,true,false>,  cudaFuncAttributeMaxDynamicSharedMemorySize, GEMM_SMEM);
    cudaFuncSetAttribute((const void*)gemm_kernel<true,false,false,false>, cudaFuncAttributeMaxDynamicSharedMemorySize, GEMM_SMEM);
    cudaFuncSetAttribute((const void*)gemm_kernel<false,true,false,true>,  cudaFuncAttributeMaxDynamicSharedMemorySize, GEMM_SMEM);
    cudaFuncSetAttribute((const void*)flash_kernel, cudaFuncAttributeMaxDynamicSharedMemorySize, FLASH_SMEM);

    const int thr = 256;
    const int t16 = DM*DM/16;     // 262144 (per-source 16-elem chunks)
    const int t8p = DM*HID/8;     // 1441792
    dim3 gq(QKVN/128, HTOK/128);  // (48,16)
    dim3 gd(DM/128,  HTOK/128);   // (16,16)
    dim3 gffh(FFN2/128, HTOK/128);// (88,16)
    dim3 gfl(SEQ/128, NH, 1);     // (16,16,1)

    // fork all three pipelines off the capture stream
    cudaEventRecord(g_e0, 0);
    cudaStreamWaitEvent(g_s1, g_e0, 0);
    cudaStreamWaitEvent(g_s2, g_e0, 0);
    cudaStreamWaitEvent(g_s3, g_e0, 0);

    // parallel qkv weight convert: one source per stream (concurrent DRAM)
    cvt_one<<<(t16+thr-1)/thr, thr, 0, g_s1>>>(wq, wqkvH, 0);
    cudaEventRecord(g_eQ1, g_s1);
    cvt_one<<<(t16+thr-1)/thr, thr, 0, g_s2>>>(wk, wqkvH, DM);
    cudaEventRecord(g_eQ2, g_s2);
    cvt_one<<<(t16+thr-1)/thr, thr, 0, g_s3>>>(wv, wqkvH, 2*DM);
    cudaEventRecord(g_eQ3, g_s3);
    // s3 continues with the remaining weight converts
    cvt_ow2<<<dim3((t8p+thr-1)/thr, 2), thr, 0, g_s3>>>(wo, w2, woH, w2H);
    cudaEventRecord(g_eW, g_s3);
    cvt_w13<<<(t8p+thr-1)/thr, thr, 0, g_s3>>>(w1, w3, w13H);
    cudaEventRecord(g_eF, g_s3);

    // ---- stream 1: batch 0 (rows 0..2047) ----
    {
        const size_t r0 = 0;
        rmsnorm_kernel<<<HTOK, 256, 0, g_s1>>>(x + r0*DM, anw, xn + r0*DM);
        cudaStreamWaitEvent(g_s1, g_eQ2, 0);
        cudaStreamWaitEvent(g_s1, g_eQ3, 0);
        gemm_kernel<false,true,true,false><<<gq, 128, GEMM_SMEM, g_s1>>>(
            xn + r0*DM, wqkvH, nullptr, qkv + r0*QKVN, HTOK, QKVN, DM, fc, fs);
        flash_kernel<<<gfl, 256, FLASH_SMEM, g_s1>>>(qkv + r0*QKVN, attn + r0*DM);
        cudaStreamWaitEvent(g_s1, g_eW, 0);
        gemm_kernel<true,false,false,false><<<gd, 128, GEMM_SMEM, g_s1>>>(
            attn + r0*DM, woH, x + r0*DM, h + r0*DM, HTOK, DM, DM, nullptr, nullptr);
        rmsnorm_kernel<<<HTOK, 256, 0, g_s1>>>(h + r0*DM, fnw, hn + r0*DM);
        cudaStreamWaitEvent(g_s1, g_eF, 0);
        gemm_kernel<false,true,false,true><<<gffh, 128, GEMM_SMEM, g_s1>>>(
            hn + r0*DM, w13H, nullptr, ffa + r0*HID, HTOK, FFN2, DM, nullptr, nullptr);
        gemm_kernel<true,false,false,false><<<gd, 128, GEMM_SMEM, g_s1>>>(
            ffa + r0*HID, w2H, h + r0*DM, out + r0*DM, HTOK, DM, HID, nullptr, nullptr);
        cudaEventRecord(g_e1, g_s1);
    }

    // ---- stream 2: batch 1 (rows 2048..4095) ----
    {
        const size_t r0 = HTOK;
        rmsnorm_kernel<<<HTOK, 256, 0, g_s2>>>(x + r0*DM, anw, xn + r0*DM);
        cudaStreamWaitEvent(g_s2, g_eQ1, 0);
        cudaStreamWaitEvent(g_s2, g_eQ3, 0);
        gemm_kernel<false,true,true,false><<<gq, 128, GEMM_SMEM, g_s2>>>(
            xn + r0*DM, wqkvH, nullptr, qkv + r0*QKVN, HTOK, QKVN, DM, fc, fs);
        flash_kernel<<<gfl, 256, FLASH_SMEM, g_s2>>>(qkv + r0*QKVN, attn + r0*DM);
        cudaStreamWaitEvent(g_s2, g_eW, 0);
        gemm_kernel<true,false,false,false><<<gd, 128, GEMM_SMEM, g_s2>>>(
            attn + r0*DM, woH, x + r0*DM, h + r0*DM, HTOK, DM, DM, nullptr, nullptr);
        rmsnorm_kernel<<<HTOK, 256, 0, g_s2>>>(h + r0*DM, fnw, hn + r0*DM);
        cudaStreamWaitEvent(g_s2, g_eF, 0);
        gemm_kernel<false,true,false,true><<<gffh, 128, GEMM_SMEM, g_s2>>>(
            hn + r0*DM, w13H, nullptr, ffa + r0*HID, HTOK, FFN2, DM, nullptr, nullptr);
        gemm_kernel<true,false,false,false><<<gd, 128, GEMM_SMEM, g_s2>>>(
            ffa + r0*HID, w2H, h + r0*DM, out + r0*DM, HTOK, DM, HID, nullptr, nullptr);
        cudaEventRecord(g_e2, g_s2);
    }

    // join back to the capture stream
    cudaStreamWaitEvent(0, g_e1, 0);
    cudaStreamWaitEvent(0, g_e2, 0);
}